// round 1
// baseline (speedup 1.0000x reference)
#include <cuda_runtime.h>
#include <cstdint>

// DGCNN: B=8, N=2048, k=32.
// Pipeline: sq -> knn -> [proj -> edge] x3 -> head1 -> head2 -> head3
// Edge-block trick: first layer feat@wa splits into per-point p/q; per-edge
// work is only lrelu(p[n]+q[nb]) followed by the Cmid x Cout GEMM + max over k.

#define NEG 0.2f
constexpr int B_  = 8;
constexpr int N_  = 2048;
constexpr int BN_ = B_ * N_;   // 16384
constexpr int K_  = 32;

// ---- scratch (device globals; no runtime allocation allowed) ----
__device__ float g_sq[BN_];
__device__ int   g_idx[BN_ * K_];
__device__ float g_p[BN_ * 128];
__device__ float g_q[BN_ * 128];
__device__ float g_x1[BN_ * 64];
__device__ float g_x2[BN_ * 128];
__device__ float g_x3[BN_ * 512];
__device__ float g_h1[BN_ * 512];
__device__ float g_h2[BN_ * 256];

__device__ __forceinline__ float lrelu(float v) { return v >= 0.f ? v : NEG * v; }

// ---------------- squared norms ----------------
__global__ void sq_kernel(const float* __restrict__ pos) {
    int i = blockIdx.x * blockDim.x + threadIdx.x;
    if (i < BN_) {
        float x = pos[i * 3 + 0];
        float y = pos[i * 3 + 1];
        float z = pos[i * 3 + 2];
        g_sq[i] = fmaf(z, z, fmaf(y, y, x * x));
    }
}

// ---------------- kNN: one block per query point ----------------
// keys[m] = (ordered(d2) << 32) | m  -> u64 min = smallest d2, ties to lowest idx
// (matches jax.lax.top_k(-d2) ordering). 32 rounds of 256->1 min with per-thread
// cached local minima; only the winning thread rescans its 8-element partition.
__global__ __launch_bounds__(256) void knn_kernel(const float* __restrict__ pos) {
    __shared__ unsigned long long keys[N_];
    __shared__ unsigned long long wmin[8];
    __shared__ unsigned long long gbest;
    int point = blockIdx.x;
    int b     = point >> 11;          // / N_
    int base  = b * N_;
    int tid   = threadIdx.x;

    float px = pos[point * 3 + 0];
    float py = pos[point * 3 + 1];
    float pz = pos[point * 3 + 2];
    float sqn = g_sq[point];

    for (int m = tid; m < N_; m += 256) {
        const float* pm = pos + (size_t)(base + m) * 3;
        float dot = fmaf(pz, pm[2], fmaf(py, pm[1], px * pm[0]));
        float d2  = (sqn - 2.f * dot) + g_sq[base + m];
        unsigned u = __float_as_uint(d2);
        u = (u & 0x80000000u) ? ~u : (u | 0x80000000u);   // order-preserving map
        keys[m] = ((unsigned long long)u << 32) | (unsigned)m;
    }
    __syncthreads();

    unsigned long long lmin = ~0ull;
#pragma unroll
    for (int i = 0; i < 8; i++) {
        unsigned long long v = keys[tid + i * 256];
        lmin = v < lmin ? v : lmin;
    }
    int lane = tid & 31, warp = tid >> 5;

    for (int it = 0; it < K_; it++) {
        unsigned long long w = lmin;
#pragma unroll
        for (int off = 16; off; off >>= 1) {
            unsigned long long o = __shfl_down_sync(0xffffffffu, w, off);
            w = o < w ? o : w;
        }
        if (lane == 0) wmin[warp] = w;
        __syncthreads();
        if (tid == 0) {
            unsigned long long g = wmin[0];
#pragma unroll
            for (int i = 1; i < 8; i++) g = wmin[i] < g ? wmin[i] : g;
            gbest = g;
            g_idx[point * K_ + it] = base + (int)(unsigned)g;  // absolute row
        }
        __syncthreads();
        unsigned long long g = gbest;
        if (lmin == g) {               // unique winner (idx embedded in key)
            keys[(unsigned)g] = ~0ull;
            lmin = ~0ull;
#pragma unroll
            for (int i = 0; i < 8; i++) {
                unsigned long long v = keys[tid + i * 256];
                lmin = v < lmin ? v : lmin;
            }
        }
    }
}

// ---------------- per-point projections p,q ----------------
// p = x @ (wa_top - wa_bot) + ba ; q = x @ wa_bot
template <int CIN, int CMID>
__global__ __launch_bounds__(CMID) void proj_kernel(const float* __restrict__ x,
                                                    const float* __restrict__ wa,
                                                    const float* __restrict__ ba) {
    __shared__ float xs[CIN];
    int point = blockIdx.x;
    int tid   = threadIdx.x;                // = cm
    if (tid < CIN) xs[tid] = x[(size_t)point * CIN + tid];
    __syncthreads();
    float pa = ba[tid], qa = 0.f;
#pragma unroll
    for (int ci = 0; ci < CIN; ci++) {
        float xv = xs[ci];
        float wt = wa[ci * CMID + tid];
        float wb = wa[(ci + CIN) * CMID + tid];
        pa = fmaf(xv, wt - wb, pa);
        qa = fmaf(xv, wb, qa);
    }
    g_p[(size_t)point * CMID + tid] = pa;
    g_q[(size_t)point * CMID + tid] = qa;
}

// ---------------- edge block: h1 build + (32 x CMID) @ (CMID x COUT) + max over k --
// h1 shared transposed [CMID][36] -> LDS.128 over 8 neighbors (broadcast).
// wb loaded row-major [cm][co0..] -> coalesced LDG across lanes.
template <int CMID, int COUT, int CT, int THREADS>
__global__ __launch_bounds__(THREADS) void edge_kernel(const float* __restrict__ wb,
                                                       const float* __restrict__ bb,
                                                       float* __restrict__ out) {
    constexpr int KPAD = 36;   // 32 + 4: keeps float4 alignment, breaks STS conflicts
    constexpr int KT   = 8;
    __shared__ int nidx[K_];
    __shared__ __align__(16) float h1t[CMID * KPAD];

    int point = blockIdx.x;
    int tid   = threadIdx.x;
    if (tid < K_) nidx[tid] = g_idx[point * K_ + tid];
    __syncthreads();

    const float* prow = g_p + (size_t)point * CMID;
    for (int e = tid; e < K_ * CMID; e += THREADS) {
        int kk = e / CMID;
        int cm = e - kk * CMID;
        float v = prow[cm] + g_q[(size_t)nidx[kk] * CMID + cm];
        h1t[cm * KPAD + kk] = lrelu(v);
    }
    __syncthreads();

    int co0 = tid * CT;
    float maxv[CT], bias[CT];
#pragma unroll
    for (int j = 0; j < CT; j++) { maxv[j] = -3.0e38f; bias[j] = bb[co0 + j]; }

    for (int kt = 0; kt < K_; kt += KT) {
        float acc[KT][CT];
#pragma unroll
        for (int i = 0; i < KT; i++)
#pragma unroll
            for (int j = 0; j < CT; j++) acc[i][j] = 0.f;

#pragma unroll 4
        for (int cm = 0; cm < CMID; cm++) {
            float4 ha = *reinterpret_cast<const float4*>(&h1t[cm * KPAD + kt]);
            float4 hb = *reinterpret_cast<const float4*>(&h1t[cm * KPAD + kt + 4]);
            float h[KT] = {ha.x, ha.y, ha.z, ha.w, hb.x, hb.y, hb.z, hb.w};
            float w[CT];
            if constexpr (CT == 4) {
                float4 w4 = *reinterpret_cast<const float4*>(&wb[cm * COUT + co0]);
                w[0] = w4.x; w[1] = w4.y; w[2] = w4.z; w[3] = w4.w;
            } else if constexpr (CT == 2) {
                float2 w2 = *reinterpret_cast<const float2*>(&wb[cm * COUT + co0]);
                w[0] = w2.x; w[1] = w2.y;
            } else {
                w[0] = wb[cm * COUT + co0];
            }
#pragma unroll
            for (int i = 0; i < KT; i++)
#pragma unroll
                for (int j = 0; j < CT; j++)
                    acc[i][j] = fmaf(h[i], w[j], acc[i][j]);
        }
#pragma unroll
        for (int i = 0; i < KT; i++)
#pragma unroll
            for (int j = 0; j < CT; j++) {
                float v = lrelu(acc[i][j] + bias[j]);
                maxv[j] = fmaxf(maxv[j], v);
            }
    }
#pragma unroll
    for (int j = 0; j < CT; j++) out[(size_t)point * COUT + co0 + j] = maxv[j];
}

// ---------------- head layer 1: concat(x1,x2,x3) [704] -> 512, lrelu -------------
__global__ __launch_bounds__(128) void head1_kernel(const float* __restrict__ wf1,
                                                    const float* __restrict__ bf1) {
    __shared__ float ins[4 * 704];
    int blk = blockIdx.x;
    int tid = threadIdx.x;
    for (int t = tid; t < 4 * 704; t += 128) {
        int r = t / 704, cm = t - r * 704;
        int row = blk * 4 + r;
        float v;
        if (cm < 64)        v = g_x1[(size_t)row * 64 + cm];
        else if (cm < 192)  v = g_x2[(size_t)row * 128 + (cm - 64)];
        else                v = g_x3[(size_t)row * 512 + (cm - 192)];
        ins[t] = v;
    }
    __syncthreads();
    int co0 = tid * 4;
    float acc[4][4];
#pragma unroll
    for (int r = 0; r < 4; r++)
#pragma unroll
        for (int j = 0; j < 4; j++) acc[r][j] = 0.f;
#pragma unroll 2
    for (int cm = 0; cm < 704; cm++) {
        float4 w4 = *reinterpret_cast<const float4*>(&wf1[cm * 512 + co0]);
#pragma unroll
        for (int r = 0; r < 4; r++) {
            float h = ins[r * 704 + cm];
            acc[r][0] = fmaf(h, w4.x, acc[r][0]);
            acc[r][1] = fmaf(h, w4.y, acc[r][1]);
            acc[r][2] = fmaf(h, w4.z, acc[r][2]);
            acc[r][3] = fmaf(h, w4.w, acc[r][3]);
        }
    }
#pragma unroll
    for (int r = 0; r < 4; r++)
#pragma unroll
        for (int j = 0; j < 4; j++) {
            float v = lrelu(acc[r][j] + bf1[co0 + j]);
            g_h1[(size_t)(blk * 4 + r) * 512 + co0 + j] = v;
        }
}

// ---------------- head layer 2: 512 -> 256, lrelu ----------------
__global__ __launch_bounds__(128) void head2_kernel(const float* __restrict__ wf2,
                                                    const float* __restrict__ bf2) {
    __shared__ float ins[4 * 512];
    int blk = blockIdx.x;
    int tid = threadIdx.x;
    for (int t = tid; t < 4 * 512; t += 128) {
        int r = t >> 9, cm = t & 511;
        ins[t] = g_h1[(size_t)(blk * 4 + r) * 512 + cm];
    }
    __syncthreads();
    int co0 = tid * 2;
    float acc[4][2];
#pragma unroll
    for (int r = 0; r < 4; r++) { acc[r][0] = 0.f; acc[r][1] = 0.f; }
#pragma unroll 4
    for (int cm = 0; cm < 512; cm++) {
        float2 w2 = *reinterpret_cast<const float2*>(&wf2[cm * 256 + co0]);
#pragma unroll
        for (int r = 0; r < 4; r++) {
            float h = ins[r * 512 + cm];
            acc[r][0] = fmaf(h, w2.x, acc[r][0]);
            acc[r][1] = fmaf(h, w2.y, acc[r][1]);
        }
    }
#pragma unroll
    for (int r = 0; r < 4; r++)
#pragma unroll
        for (int j = 0; j < 2; j++) {
            float v = lrelu(acc[r][j] + bf2[co0 + j]);
            g_h2[(size_t)(blk * 4 + r) * 256 + co0 + j] = v;
        }
}

// ---------------- head layer 3: 256 -> 12 (no lrelu) ----------------
__global__ __launch_bounds__(32) void head3_kernel(const float* __restrict__ wf3,
                                                   const float* __restrict__ bf3,
                                                   float* __restrict__ out) {
    int row = blockIdx.x;
    int tid = threadIdx.x;
    if (tid < 12) {
        float a0 = bf3[tid], a1 = 0.f, a2 = 0.f, a3 = 0.f;
        const float* h = g_h2 + (size_t)row * 256;
#pragma unroll 4
        for (int cm = 0; cm < 256; cm += 4) {
            a0 = fmaf(h[cm + 0], wf3[(cm + 0) * 12 + tid], a0);
            a1 = fmaf(h[cm + 1], wf3[(cm + 1) * 12 + tid], a1);
            a2 = fmaf(h[cm + 2], wf3[(cm + 2) * 12 + tid], a2);
            a3 = fmaf(h[cm + 3], wf3[(cm + 3) * 12 + tid], a3);
        }
        out[(size_t)row * 12 + tid] = (a0 + a1) + (a2 + a3);
    }
}

// ---------------- launch ----------------
extern "C" void kernel_launch(void* const* d_in, const int* in_sizes, int n_in,
                              void* d_out, int out_size) {
    const float* x   = (const float*)d_in[0];
    const float* pos = (const float*)d_in[1];
    const float* w1a = (const float*)d_in[2];
    const float* b1a = (const float*)d_in[3];
    const float* w1b = (const float*)d_in[4];
    const float* b1b = (const float*)d_in[5];
    const float* w2a = (const float*)d_in[6];
    const float* b2a = (const float*)d_in[7];
    const float* w2b = (const float*)d_in[8];
    const float* b2b = (const float*)d_in[9];
    const float* w3a = (const float*)d_in[10];
    const float* b3a = (const float*)d_in[11];
    const float* w3b = (const float*)d_in[12];
    const float* b3b = (const float*)d_in[13];
    const float* wf1 = (const float*)d_in[14];
    const float* bf1 = (const float*)d_in[15];
    const float* wf2 = (const float*)d_in[16];
    const float* bf2 = (const float*)d_in[17];
    const float* wf3 = (const float*)d_in[18];
    const float* bf3 = (const float*)d_in[19];
    float* out = (float*)d_out;

    float *x1p = nullptr, *x2p = nullptr, *x3p = nullptr;
    cudaGetSymbolAddress((void**)&x1p, g_x1);
    cudaGetSymbolAddress((void**)&x2p, g_x2);
    cudaGetSymbolAddress((void**)&x3p, g_x3);

    sq_kernel<<<BN_ / 256, 256>>>(pos);
    knn_kernel<<<BN_, 256>>>(pos);

    // block1: 3 -> 64 -> 64
    proj_kernel<3, 64><<<BN_, 64>>>(x, w1a, b1a);
    edge_kernel<64, 64, 1, 64><<<BN_, 64>>>(w1b, b1b, x1p);
    // block2: 64 -> 64 -> 128
    proj_kernel<64, 64><<<BN_, 64>>>(x1p, w2a, b2a);
    edge_kernel<64, 128, 2, 64><<<BN_, 64>>>(w2b, b2b, x2p);
    // block3: 128 -> 128 -> 512
    proj_kernel<128, 128><<<BN_, 128>>>(x2p, w3a, b3a);
    edge_kernel<128, 512, 4, 128><<<BN_, 128>>>(w3b, b3b, x3p);

    // head
    head1_kernel<<<BN_ / 4, 128>>>(wf1, bf1);
    head2_kernel<<<BN_ / 4, 128>>>(wf2, bf2);
    head3_kernel<<<BN_, 32>>>(wf3, bf3, out);
}

// round 2
// speedup vs baseline: 1.0468x; 1.0468x over previous
#include <cuda_runtime.h>
#include <cstdint>

// DGCNN: B=8, N=2048, k=32.
// sq -> knn -> [proj -> edge] x3 -> head1 -> head2 -> head3
// Edge-block trick: first layer feat@wa splits into per-point p/q; per-edge
// work is lrelu(p[n]+q[nb]) then Cmid x Cout GEMM + max over k.
// Round 2: edge3 (32x128 @ 128x512 per point, 34.4 G-FMA) moved to tensor
// pipe via mma.sync m16n8k8 tf32.

#define NEG 0.2f
constexpr int B_  = 8;
constexpr int N_  = 2048;
constexpr int BN_ = B_ * N_;   // 16384
constexpr int K_  = 32;

// ---- scratch (device globals; no runtime allocation allowed) ----
__device__ float g_sq[BN_];
__device__ int   g_idx[BN_ * K_];
__device__ float g_p[BN_ * 128];
__device__ float g_q[BN_ * 128];
__device__ float g_x1[BN_ * 64];
__device__ float g_x2[BN_ * 128];
__device__ float g_x3[BN_ * 512];
__device__ float g_h1[BN_ * 512];
__device__ float g_h2[BN_ * 256];

__device__ __forceinline__ float lrelu(float v) { return v >= 0.f ? v : NEG * v; }

__device__ __forceinline__ unsigned f2tf32(float x) {
    unsigned r;
    asm("cvt.rna.tf32.f32 %0, %1;" : "=r"(r) : "f"(x));
    return r;
}

__device__ __forceinline__ void mma_tf32(float d[4], const unsigned a[4], const unsigned b[2]) {
    asm volatile(
        "mma.sync.aligned.m16n8k8.row.col.f32.tf32.tf32.f32 "
        "{%0,%1,%2,%3}, {%4,%5,%6,%7}, {%8,%9}, {%0,%1,%2,%3};\n"
        : "+f"(d[0]), "+f"(d[1]), "+f"(d[2]), "+f"(d[3])
        : "r"(a[0]), "r"(a[1]), "r"(a[2]), "r"(a[3]), "r"(b[0]), "r"(b[1]));
}

// ---------------- squared norms ----------------
__global__ void sq_kernel(const float* __restrict__ pos) {
    int i = blockIdx.x * blockDim.x + threadIdx.x;
    if (i < BN_) {
        float x = pos[i * 3 + 0];
        float y = pos[i * 3 + 1];
        float z = pos[i * 3 + 2];
        g_sq[i] = fmaf(z, z, fmaf(y, y, x * x));
    }
}

// ---------------- kNN: one block per query point ----------------
__global__ __launch_bounds__(256) void knn_kernel(const float* __restrict__ pos) {
    __shared__ unsigned long long keys[N_];
    __shared__ unsigned long long wmin[8];
    __shared__ unsigned long long gbest;
    int point = blockIdx.x;
    int b     = point >> 11;
    int base  = b * N_;
    int tid   = threadIdx.x;

    float px = pos[point * 3 + 0];
    float py = pos[point * 3 + 1];
    float pz = pos[point * 3 + 2];
    float sqn = g_sq[point];

    for (int m = tid; m < N_; m += 256) {
        const float* pm = pos + (size_t)(base + m) * 3;
        float dot = fmaf(pz, pm[2], fmaf(py, pm[1], px * pm[0]));
        float d2  = (sqn - 2.f * dot) + g_sq[base + m];
        unsigned u = __float_as_uint(d2);
        u = (u & 0x80000000u) ? ~u : (u | 0x80000000u);
        keys[m] = ((unsigned long long)u << 32) | (unsigned)m;
    }
    __syncthreads();

    unsigned long long lmin = ~0ull;
#pragma unroll
    for (int i = 0; i < 8; i++) {
        unsigned long long v = keys[tid + i * 256];
        lmin = v < lmin ? v : lmin;
    }
    int lane = tid & 31, warp = tid >> 5;

    for (int it = 0; it < K_; it++) {
        unsigned long long w = lmin;
#pragma unroll
        for (int off = 16; off; off >>= 1) {
            unsigned long long o = __shfl_down_sync(0xffffffffu, w, off);
            w = o < w ? o : w;
        }
        if (lane == 0) wmin[warp] = w;
        __syncthreads();
        if (tid == 0) {
            unsigned long long g = wmin[0];
#pragma unroll
            for (int i = 1; i < 8; i++) g = wmin[i] < g ? wmin[i] : g;
            gbest = g;
            g_idx[point * K_ + it] = base + (int)(unsigned)g;
        }
        __syncthreads();
        unsigned long long g = gbest;
        if (lmin == g) {
            keys[(unsigned)g] = ~0ull;
            lmin = ~0ull;
#pragma unroll
            for (int i = 0; i < 8; i++) {
                unsigned long long v = keys[tid + i * 256];
                lmin = v < lmin ? v : lmin;
            }
        }
    }
}

// ---------------- per-point projections p,q ----------------
template <int CIN, int CMID>
__global__ __launch_bounds__(CMID) void proj_kernel(const float* __restrict__ x,
                                                    const float* __restrict__ wa,
                                                    const float* __restrict__ ba) {
    __shared__ float xs[CIN];
    int point = blockIdx.x;
    int tid   = threadIdx.x;
    if (tid < CIN) xs[tid] = x[(size_t)point * CIN + tid];
    __syncthreads();
    float pa = ba[tid], qa = 0.f;
#pragma unroll
    for (int ci = 0; ci < CIN; ci++) {
        float xv = xs[ci];
        float wt = wa[ci * CMID + tid];
        float wb = wa[(ci + CIN) * CMID + tid];
        pa = fmaf(xv, wt - wb, pa);
        qa = fmaf(xv, wb, qa);
    }
    g_p[(size_t)point * CMID + tid] = pa;
    g_q[(size_t)point * CMID + tid] = qa;
}

// ---------------- edge blocks 1,2 (fp32 FFMA path) ----------------
template <int CMID, int COUT, int CT, int THREADS>
__global__ __launch_bounds__(THREADS) void edge_kernel(const float* __restrict__ wb,
                                                       const float* __restrict__ bb,
                                                       float* __restrict__ out) {
    constexpr int KPAD = 36;
    constexpr int KT   = 8;
    __shared__ int nidx[K_];
    __shared__ __align__(16) float h1t[CMID * KPAD];

    int point = blockIdx.x;
    int tid   = threadIdx.x;
    if (tid < K_) nidx[tid] = g_idx[point * K_ + tid];
    __syncthreads();

    const float* prow = g_p + (size_t)point * CMID;
    for (int e = tid; e < K_ * CMID; e += THREADS) {
        int kk = e / CMID;
        int cm = e - kk * CMID;
        float v = prow[cm] + g_q[(size_t)nidx[kk] * CMID + cm];
        h1t[cm * KPAD + kk] = lrelu(v);
    }
    __syncthreads();

    int co0 = tid * CT;
    float maxv[CT], bias[CT];
#pragma unroll
    for (int j = 0; j < CT; j++) { maxv[j] = -3.0e38f; bias[j] = bb[co0 + j]; }

    for (int kt = 0; kt < K_; kt += KT) {
        float acc[KT][CT];
#pragma unroll
        for (int i = 0; i < KT; i++)
#pragma unroll
            for (int j = 0; j < CT; j++) acc[i][j] = 0.f;

#pragma unroll 4
        for (int cm = 0; cm < CMID; cm++) {
            float4 ha = *reinterpret_cast<const float4*>(&h1t[cm * KPAD + kt]);
            float4 hb = *reinterpret_cast<const float4*>(&h1t[cm * KPAD + kt + 4]);
            float h[KT] = {ha.x, ha.y, ha.z, ha.w, hb.x, hb.y, hb.z, hb.w};
            float w[CT];
            if constexpr (CT == 4) {
                float4 w4 = *reinterpret_cast<const float4*>(&wb[cm * COUT + co0]);
                w[0] = w4.x; w[1] = w4.y; w[2] = w4.z; w[3] = w4.w;
            } else if constexpr (CT == 2) {
                float2 w2 = *reinterpret_cast<const float2*>(&wb[cm * COUT + co0]);
                w[0] = w2.x; w[1] = w2.y;
            } else {
                w[0] = wb[cm * COUT + co0];
            }
#pragma unroll
            for (int i = 0; i < KT; i++)
#pragma unroll
                for (int j = 0; j < CT; j++)
                    acc[i][j] = fmaf(h[i], w[j], acc[i][j]);
        }
#pragma unroll
        for (int i = 0; i < KT; i++)
#pragma unroll
            for (int j = 0; j < CT; j++) {
                float v = lrelu(acc[i][j] + bias[j]);
                maxv[j] = fmaxf(maxv[j], v);
            }
    }
#pragma unroll
    for (int j = 0; j < CT; j++) out[(size_t)point * COUT + co0 + j] = maxv[j];
}

// ---------------- edge block 3 via tf32 tensor-core mma ----------------
// Per block: 8 points (A = 8 x [32 x 128] edge features) x 128 output cols.
// 16 warps; warp = (point, 64-col half): 2 m16-tiles x 8 n8-tiles, K-loop 16x k8.
// smem strides 132/136 make all fragment LDS bank-conflict-free.
constexpr int E3_PT   = 8;
constexpr int E3_NT   = 128;
constexpr int E3_ASTR = 132;
constexpr int E3_BSTR = 136;
constexpr int E3_SB_WORDS = 128 * E3_BSTR;        // 17408
constexpr int E3_SA_WORDS = E3_PT * 32 * E3_ASTR; // 33792
constexpr size_t E3_SMEM = (size_t)(E3_SB_WORDS + E3_SA_WORDS) * 4 + E3_PT * K_ * 4; // 205824

__global__ __launch_bounds__(512) void edge3_mma_kernel(const float* __restrict__ wb,
                                                        const float* __restrict__ bb,
                                                        float* __restrict__ out) {
    extern __shared__ unsigned smem_u[];
    unsigned* sB = smem_u;
    unsigned* sA = smem_u + E3_SB_WORDS;
    int* nidx    = (int*)(smem_u + E3_SB_WORDS + E3_SA_WORDS);

    int tid = threadIdx.x;
    int p0  = blockIdx.x * E3_PT;
    int nb0 = blockIdx.y * E3_NT;

    if (tid < E3_PT * K_) nidx[tid] = g_idx[p0 * K_ + tid];

    // B tile: w3b[0:128][nb0 : nb0+128] -> tf32, stride 136
#pragma unroll 4
    for (int i = 0; i < 32; i++) {
        int idx = i * 512 + tid;
        int r = idx >> 7, c = idx & 127;
        sB[r * E3_BSTR + c] = f2tf32(wb[r * 512 + nb0 + c]);
    }
    __syncthreads();   // nidx ready

    // A tile: 256 rows (8 points x 32 nbrs) x 128, lrelu(p + q[nb]), stride 132
#pragma unroll 4
    for (int i = 0; i < 64; i++) {
        int idx = i * 512 + tid;
        int r = idx >> 7, cm = idx & 127;
        int pl = r >> 5;
        float v = g_p[(size_t)(p0 + pl) * 128 + cm] + g_q[(size_t)nidx[r] * 128 + cm];
        sA[r * E3_ASTR + cm] = f2tf32(lrelu(v));
    }
    __syncthreads();

    int w = tid >> 5, lane = tid & 31;
    int pl = w >> 1;               // point within block
    int nh = (w & 1) * 64;         // col half
    int gid = lane >> 2, tig = lane & 3;

    float acc[2][8][4];
#pragma unroll
    for (int mt = 0; mt < 2; mt++)
#pragma unroll
        for (int nt = 0; nt < 8; nt++)
#pragma unroll
            for (int j = 0; j < 4; j++) acc[mt][nt][j] = 0.f;

#pragma unroll 1
    for (int ks = 0; ks < 16; ks++) {
        unsigned a[2][4];
#pragma unroll
        for (int mt = 0; mt < 2; mt++) {
            const unsigned* Ar = sA + (pl * 32 + mt * 16 + gid) * E3_ASTR + ks * 8 + tig;
            a[mt][0] = Ar[0];
            a[mt][1] = Ar[8 * E3_ASTR];
            a[mt][2] = Ar[4];
            a[mt][3] = Ar[8 * E3_ASTR + 4];
        }
        const unsigned* Br = sB + (ks * 8 + tig) * E3_BSTR + nh + gid;
#pragma unroll
        for (int nt = 0; nt < 8; nt++) {
            unsigned b[2] = { Br[nt * 8], Br[4 * E3_BSTR + nt * 8] };
            mma_tf32(acc[0][nt], a[0], b);
            mma_tf32(acc[1][nt], a[1], b);
        }
    }

    // epilogue: colmax over 32 k-rows, then lrelu(max + bias)  (lrelu monotone)
    int pglob = p0 + pl;
#pragma unroll
    for (int nt = 0; nt < 8; nt++) {
        float v0 = fmaxf(fmaxf(acc[0][nt][0], acc[0][nt][2]),
                         fmaxf(acc[1][nt][0], acc[1][nt][2]));
        float v1 = fmaxf(fmaxf(acc[0][nt][1], acc[0][nt][3]),
                         fmaxf(acc[1][nt][1], acc[1][nt][3]));
#pragma unroll
        for (int s = 4; s < 32; s <<= 1) {
            v0 = fmaxf(v0, __shfl_xor_sync(0xffffffffu, v0, s));
            v1 = fmaxf(v1, __shfl_xor_sync(0xffffffffu, v1, s));
        }
        if (lane < 4) {
            int col = nb0 + nh + nt * 8 + 2 * lane;
            out[(size_t)pglob * 512 + col]     = lrelu(v0 + bb[col]);
            out[(size_t)pglob * 512 + col + 1] = lrelu(v1 + bb[col + 1]);
        }
    }
}

// ---------------- head layer 1: concat(x1,x2,x3) [704] -> 512, lrelu ------------
__global__ __launch_bounds__(128) void head1_kernel(const float* __restrict__ wf1,
                                                    const float* __restrict__ bf1) {
    __shared__ float ins[4 * 704];
    int blk = blockIdx.x;
    int tid = threadIdx.x;
    for (int t = tid; t < 4 * 704; t += 128) {
        int r = t / 704, cm = t - r * 704;
        int row = blk * 4 + r;
        float v;
        if (cm < 64)        v = g_x1[(size_t)row * 64 + cm];
        else if (cm < 192)  v = g_x2[(size_t)row * 128 + (cm - 64)];
        else                v = g_x3[(size_t)row * 512 + (cm - 192)];
        ins[t] = v;
    }
    __syncthreads();
    int co0 = tid * 4;
    float acc[4][4];
#pragma unroll
    for (int r = 0; r < 4; r++)
#pragma unroll
        for (int j = 0; j < 4; j++) acc[r][j] = 0.f;
#pragma unroll 2
    for (int cm = 0; cm < 704; cm++) {
        float4 w4 = *reinterpret_cast<const float4*>(&wf1[cm * 512 + co0]);
#pragma unroll
        for (int r = 0; r < 4; r++) {
            float h = ins[r * 704 + cm];
            acc[r][0] = fmaf(h, w4.x, acc[r][0]);
            acc[r][1] = fmaf(h, w4.y, acc[r][1]);
            acc[r][2] = fmaf(h, w4.z, acc[r][2]);
            acc[r][3] = fmaf(h, w4.w, acc[r][3]);
        }
    }
#pragma unroll
    for (int r = 0; r < 4; r++)
#pragma unroll
        for (int j = 0; j < 4; j++) {
            float v = lrelu(acc[r][j] + bf1[co0 + j]);
            g_h1[(size_t)(blk * 4 + r) * 512 + co0 + j] = v;
        }
}

// ---------------- head layer 2: 512 -> 256, lrelu ----------------
__global__ __launch_bounds__(128) void head2_kernel(const float* __restrict__ wf2,
                                                    const float* __restrict__ bf2) {
    __shared__ float ins[4 * 512];
    int blk = blockIdx.x;
    int tid = threadIdx.x;
    for (int t = tid; t < 4 * 512; t += 128) {
        int r = t >> 9, cm = t & 511;
        ins[t] = g_h1[(size_t)(blk * 4 + r) * 512 + cm];
    }
    __syncthreads();
    int co0 = tid * 2;
    float acc[4][2];
#pragma unroll
    for (int r = 0; r < 4; r++) { acc[r][0] = 0.f; acc[r][1] = 0.f; }
#pragma unroll 4
    for (int cm = 0; cm < 512; cm++) {
        float2 w2 = *reinterpret_cast<const float2*>(&wf2[cm * 256 + co0]);
#pragma unroll
        for (int r = 0; r < 4; r++) {
            float h = ins[r * 512 + cm];
            acc[r][0] = fmaf(h, w2.x, acc[r][0]);
            acc[r][1] = fmaf(h, w2.y, acc[r][1]);
        }
    }
#pragma unroll
    for (int r = 0; r < 4; r++)
#pragma unroll
        for (int j = 0; j < 2; j++) {
            float v = lrelu(acc[r][j] + bf2[co0 + j]);
            g_h2[(size_t)(blk * 4 + r) * 256 + co0 + j] = v;
        }
}

// ---------------- head layer 3: 256 -> 12 (no lrelu) ----------------
__global__ __launch_bounds__(32) void head3_kernel(const float* __restrict__ wf3,
                                                   const float* __restrict__ bf3,
                                                   float* __restrict__ out) {
    int row = blockIdx.x;
    int tid = threadIdx.x;
    if (tid < 12) {
        float a0 = bf3[tid], a1 = 0.f, a2 = 0.f, a3 = 0.f;
        const float* h = g_h2 + (size_t)row * 256;
#pragma unroll 4
        for (int cm = 0; cm < 256; cm += 4) {
            a0 = fmaf(h[cm + 0], wf3[(cm + 0) * 12 + tid], a0);
            a1 = fmaf(h[cm + 1], wf3[(cm + 1) * 12 + tid], a1);
            a2 = fmaf(h[cm + 2], wf3[(cm + 2) * 12 + tid], a2);
            a3 = fmaf(h[cm + 3], wf3[(cm + 3) * 12 + tid], a3);
        }
        out[(size_t)row * 12 + tid] = (a0 + a1) + (a2 + a3);
    }
}

// ---------------- launch ----------------
extern "C" void kernel_launch(void* const* d_in, const int* in_sizes, int n_in,
                              void* d_out, int out_size) {
    const float* x   = (const float*)d_in[0];
    const float* pos = (const float*)d_in[1];
    const float* w1a = (const float*)d_in[2];
    const float* b1a = (const float*)d_in[3];
    const float* w1b = (const float*)d_in[4];
    const float* b1b = (const float*)d_in[5];
    const float* w2a = (const float*)d_in[6];
    const float* b2a = (const float*)d_in[7];
    const float* w2b = (const float*)d_in[8];
    const float* b2b = (const float*)d_in[9];
    const float* w3a = (const float*)d_in[10];
    const float* b3a = (const float*)d_in[11];
    const float* w3b = (const float*)d_in[12];
    const float* b3b = (const float*)d_in[13];
    const float* wf1 = (const float*)d_in[14];
    const float* bf1 = (const float*)d_in[15];
    const float* wf2 = (const float*)d_in[16];
    const float* bf2 = (const float*)d_in[17];
    const float* wf3 = (const float*)d_in[18];
    const float* bf3 = (const float*)d_in[19];
    float* out = (float*)d_out;

    float *x1p = nullptr, *x2p = nullptr, *x3p = nullptr;
    cudaGetSymbolAddress((void**)&x1p, g_x1);
    cudaGetSymbolAddress((void**)&x2p, g_x2);
    cudaGetSymbolAddress((void**)&x3p, g_x3);

    static bool attr_done = false;
    if (!attr_done) {
        cudaFuncSetAttribute(edge3_mma_kernel,
                             cudaFuncAttributeMaxDynamicSharedMemorySize,
                             (int)E3_SMEM);
        attr_done = true;
    }

    sq_kernel<<<BN_ / 256, 256>>>(pos);
    knn_kernel<<<BN_, 256>>>(pos);

    // block1: 3 -> 64 -> 64
    proj_kernel<3, 64><<<BN_, 64>>>(x, w1a, b1a);
    edge_kernel<64, 64, 1, 64><<<BN_, 64>>>(w1b, b1b, x1p);
    // block2: 64 -> 64 -> 128
    proj_kernel<64, 64><<<BN_, 64>>>(x1p, w2a, b2a);
    edge_kernel<64, 128, 2, 64><<<BN_, 64>>>(w2b, b2b, x2p);
    // block3: 128 -> 128 -> 512  (tensor-core path)
    proj_kernel<128, 128><<<BN_, 128>>>(x2p, w3a, b3a);
    edge3_mma_kernel<<<dim3(BN_ / E3_PT, 512 / E3_NT), 512, E3_SMEM>>>(w3b, b3b, x3p);

    // head
    head1_kernel<<<BN_ / 4, 128>>>(wf1, bf1);
    head2_kernel<<<BN_ / 4, 128>>>(wf2, bf2);
    head3_kernel<<<BN_, 32>>>(wf3, bf3, out);
}

// round 5
// speedup vs baseline: 1.6035x; 1.5318x over previous
#include <cuda_runtime.h>
#include <cuda_fp16.h>
#include <cstdint>

// DGCNN: B=8, N=2048, k=32.  (sm_103 PTX target: no tcgen05 -> mma.sync f16)
// sq -> proj1 -> prep(wbT f16) -> knn -> edge1/2/3 (f16 mma) -> fused head.
// Edge trick: feat@wa = p[point] + q[neighbor]; per-edge work is
// lrelu(p+q) then CMID x COUT GEMM + max over k (lrelu monotone -> max last).

#define NEG 0.2f
constexpr int B_  = 8;
constexpr int N_  = 2048;
constexpr int BN_ = B_ * N_;   // 16384
constexpr int K_  = 32;

// ---- scratch (device globals; no runtime allocation allowed) ----
__device__ float  g_sq[BN_];
__device__ int    g_idx[BN_ * K_];
__device__ float  g_p[BN_ * 128];
__device__ float  g_q[BN_ * 128];
__device__ float  g_x1[BN_ * 64];
__device__ float  g_x2[BN_ * 128];
__device__ float  g_x3[BN_ * 512];
__device__ __half g_wbT1[64 * 64];     // w1b^T [64][64]
__device__ __half g_wbT2[128 * 64];    // w2b^T [128][64]
__device__ __half g_wbT3[512 * 128];   // w3b^T [512][128]

__device__ __forceinline__ float lrelu(float v) { return v >= 0.f ? v : NEG * v; }

__device__ __forceinline__ uint32_t pack_f16x2(float lo, float hi) {
    uint32_t u;
    asm("cvt.rn.f16x2.f32 %0, %1, %2;" : "=r"(u) : "f"(hi), "f"(lo));
    return u;
}

__device__ __forceinline__ void mma16816(float d[4], const uint32_t a[4],
                                         const uint32_t b[2]) {
    asm volatile(
        "mma.sync.aligned.m16n8k16.row.col.f32.f16.f16.f32 "
        "{%0,%1,%2,%3}, {%4,%5,%6,%7}, {%8,%9}, {%0,%1,%2,%3};\n"
        : "+f"(d[0]), "+f"(d[1]), "+f"(d[2]), "+f"(d[3])
        : "r"(a[0]), "r"(a[1]), "r"(a[2]), "r"(a[3]), "r"(b[0]), "r"(b[1]));
}

// ---------------- squared norms ----------------
__global__ void sq_kernel(const float* __restrict__ pos) {
    int i = blockIdx.x * blockDim.x + threadIdx.x;
    if (i < BN_) {
        float x = pos[i * 3 + 0], y = pos[i * 3 + 1], z = pos[i * 3 + 2];
        g_sq[i] = fmaf(z, z, fmaf(y, y, x * x));
    }
}

// ---------------- weight transpose + f16 prep (range [t0, t0+cnt)) ------------
__global__ void prep_wbT(const float* __restrict__ w, __half* __restrict__ wt,
                         int Kd, int Nd, int t0, int cnt) {
    int local = blockIdx.x * 256 + threadIdx.x;
    if (local < cnt) {
        int t = t0 + local;
        int k = t / Nd, n = t - k * Nd;
        wt[n * Kd + k] = __float2half_rn(w[t]);
    }
}

// ---------------- kNN: barrier-light hierarchical selection ----------------
// Warp w computes 256 distances (8/lane, registers), selects its top-32 via
// shfl_xor min rounds (no block barrier). Warp 0 then merges 8x32 candidates.
// Key = (ordered(d2) << 32) | idx  ==> asc d2, tie lowest idx (= lax.top_k).
__global__ __launch_bounds__(256) void knn_kernel(const float* __restrict__ pos) {
    __shared__ unsigned long long cand[256];
    int point = blockIdx.x;
    int base  = (point >> 11) * N_;
    int tid   = threadIdx.x;
    int w     = tid >> 5, lane = tid & 31;

    float px = pos[point * 3 + 0], py = pos[point * 3 + 1], pz = pos[point * 3 + 2];
    float sqn = g_sq[point];

    unsigned long long k[8];
#pragma unroll
    for (int i = 0; i < 8; i++) {
        int m = (w << 8) + (i << 5) + lane;
        const float* pm = pos + (size_t)(base + m) * 3;
        float dot = fmaf(pz, pm[2], fmaf(py, pm[1], px * pm[0]));
        float d2  = (sqn - 2.f * dot) + g_sq[base + m];
        unsigned u = __float_as_uint(d2);
        u = (u & 0x80000000u) ? ~u : (u | 0x80000000u);
        k[i] = ((unsigned long long)u << 32) | (unsigned)m;
    }
    unsigned long long lmin = k[0];
#pragma unroll
    for (int i = 1; i < 8; i++) lmin = k[i] < lmin ? k[i] : lmin;

#pragma unroll 1
    for (int it = 0; it < K_; it++) {
        unsigned long long mn = lmin;
#pragma unroll
        for (int off = 16; off; off >>= 1) {
            unsigned long long o = __shfl_xor_sync(0xffffffffu, mn, off);
            mn = o < mn ? o : mn;
        }
        if (lane == 0) cand[(w << 5) + it] = mn;
        if (lmin == mn) {
#pragma unroll
            for (int i = 0; i < 8; i++) if (k[i] == mn) k[i] = ~0ull;
            lmin = k[0];
#pragma unroll
            for (int i = 1; i < 8; i++) lmin = k[i] < lmin ? k[i] : lmin;
        }
    }
    __syncthreads();

    if (w == 0) {
        unsigned long long c[8];
#pragma unroll
        for (int i = 0; i < 8; i++) c[i] = cand[(i << 5) + lane];
        unsigned long long lm = c[0];
#pragma unroll
        for (int i = 1; i < 8; i++) lm = c[i] < lm ? c[i] : lm;
#pragma unroll 1
        for (int it = 0; it < K_; it++) {
            unsigned long long mn = lm;
#pragma unroll
            for (int off = 16; off; off >>= 1) {
                unsigned long long o = __shfl_xor_sync(0xffffffffu, mn, off);
                mn = o < mn ? o : mn;
            }
            if (lane == 0) g_idx[point * K_ + it] = base + (int)(unsigned)mn;
            if (lm == mn) {
#pragma unroll
                for (int i = 0; i < 8; i++) if (c[i] == mn) c[i] = ~0ull;
                lm = c[0];
#pragma unroll
                for (int i = 1; i < 8; i++) lm = c[i] < lm ? c[i] : lm;
            }
        }
    }
}

// ---------------- batched per-point projections p,q ----------------
// 32 points per block; weights staged in smem once (kills L2 re-read traffic).
// p = x @ (wa_top - wa_bot) + ba ; q = x @ wa_bot
template <int CIN, int CMID, int CINP>
__global__ __launch_bounds__(256) void proj_kernel(const float* __restrict__ x,
                                                   const float* __restrict__ wa,
                                                   const float* __restrict__ ba) {
    extern __shared__ __align__(16) float smf[];
    float* wts = smf;                      // [CMID][CINP]
    float* wqs = wts + CMID * CINP;        // [CMID][CINP]
    float* xs  = wqs + CMID * CINP;        // [32][CINP]
    float* bas = xs + 32 * CINP;           // [CMID]
    int tid = threadIdx.x;
    int p0  = blockIdx.x * 32;

    for (int t = tid; t < CIN * CMID; t += 256) {
        int ci = t / CMID, cm = t - ci * CMID;
        float top = wa[t], bot = wa[CIN * CMID + t];
        wts[cm * CINP + ci] = top - bot;
        wqs[cm * CINP + ci] = bot;
    }
    for (int t = tid; t < 32 * CIN; t += 256) {
        int pp = t / CIN, ci = t - pp * CIN;
        xs[pp * CINP + ci] = x[(size_t)(p0 + pp) * CIN + ci];
    }
    if (tid < CMID) bas[tid] = ba[tid];
    __syncthreads();

    constexpr int LANES = 256 / CMID;
    int li = tid / CMID, cm = tid - li * CMID;
    const float* wtr = wts + cm * CINP;
    const float* wqr = wqs + cm * CINP;
    float bias = bas[cm];

    for (int pp = li; pp < 32; pp += LANES) {
        const float* xr = xs + pp * CINP;
        float pa = bias, qa = 0.f;
        if constexpr (CIN % 4 == 0) {
#pragma unroll
            for (int ci = 0; ci < CIN; ci += 4) {
                float4 xv = *(const float4*)(xr + ci);
                float4 wt4 = *(const float4*)(wtr + ci);
                float4 wq4 = *(const float4*)(wqr + ci);
                pa = fmaf(xv.x, wt4.x, pa); qa = fmaf(xv.x, wq4.x, qa);
                pa = fmaf(xv.y, wt4.y, pa); qa = fmaf(xv.y, wq4.y, qa);
                pa = fmaf(xv.z, wt4.z, pa); qa = fmaf(xv.z, wq4.z, qa);
                pa = fmaf(xv.w, wt4.w, pa); qa = fmaf(xv.w, wq4.w, qa);
            }
        } else {
#pragma unroll
            for (int ci = 0; ci < CIN; ci++) {
                float xv = xr[ci];
                pa = fmaf(xv, wtr[ci], pa);
                qa = fmaf(xv, wqr[ci], qa);
            }
        }
        g_p[(size_t)(p0 + pp) * CMID + cm] = pa;
        g_q[(size_t)(p0 + pp) * CMID + cm] = qa;
    }
}

// ---------------- edge blocks via mma.sync m16n8k16 f16 ----------------
// Block: PT points (A = PT*32 edge rows, f16), N-tile NT cols of wbT.
// 512 threads, 16 warps; warp = (point, 64-col group): 2 m16 x 8 n8, K step 16.
// Epilogue: colmax over 32 k-rows in regs+shfl, lrelu(max + bias) (monotone).
template <int CMID, int COUT, int PT, int NT>
__global__ __launch_bounds__(512) void edge_mma(const __half* __restrict__ wbT,
                                                const float* __restrict__ bb,
                                                float* __restrict__ out) {
    constexpr int KP    = CMID + 8;        // halves; (KP/2)%32==4 -> conflict-free
    constexpr int AROWS = PT * 32;
    constexpr int CPR8  = CMID / 8;        // 8-half chunks per row
    extern __shared__ __align__(16) char smraw[];
    __half* As = (__half*)smraw;                    // [AROWS][KP]
    __half* Bs = As + AROWS * KP;                   // [NT][KP]
    int*  nidx = (int*)(Bs + NT * KP);              // [AROWS]

    int tid = threadIdx.x, w = tid >> 5, lane = tid & 31;
    int p0 = blockIdx.x * PT, n0 = blockIdx.y * NT;

    for (int t = tid; t < AROWS; t += 512) nidx[t] = g_idx[p0 * K_ + t];
    __syncthreads();

    // A fill: row r=(pt,nbr): lrelu(p + q[nb]) -> f16
#pragma unroll
    for (int i = 0; i < AROWS * CPR8 / 512; i++) {
        int e  = i * 512 + tid;
        int r  = e / CPR8;
        int c0 = (e - r * CPR8) * 8;
        const float* qr = g_q + (size_t)nidx[r] * CMID + c0;
        const float* pr = g_p + (size_t)(p0 + (r >> 5)) * CMID + c0;
        float4 qa = *(const float4*)qr, qb = *(const float4*)(qr + 4);
        float4 pa = *(const float4*)pr, pb = *(const float4*)(pr + 4);
        uint4 pk = { pack_f16x2(lrelu(pa.x + qa.x), lrelu(pa.y + qa.y)),
                     pack_f16x2(lrelu(pa.z + qa.z), lrelu(pa.w + qa.w)),
                     pack_f16x2(lrelu(pb.x + qb.x), lrelu(pb.y + qb.y)),
                     pack_f16x2(lrelu(pb.z + qb.z), lrelu(pb.w + qb.w)) };
        *(uint4*)(As + r * KP + c0) = pk;
    }
    // B fill: Bs[n][k] from f16 wbT[COUT][CMID]
#pragma unroll
    for (int i = 0; i < NT * CPR8 / 512; i++) {
        int e  = i * 512 + tid;
        int r  = e / CPR8;
        int c0 = (e - r * CPR8) * 8;
        *(uint4*)(Bs + r * KP + c0) =
            *(const uint4*)(wbT + (size_t)(n0 + r) * CMID + c0);
    }
    __syncthreads();

    constexpr int NHW = NT / 64;
    int pl = w / NHW;
    int nh = (w % NHW) * 64;
    int gid = lane >> 2, tig = lane & 3;

    float acc[2][8][4];
#pragma unroll
    for (int mt = 0; mt < 2; mt++)
#pragma unroll
        for (int nt = 0; nt < 8; nt++)
#pragma unroll
            for (int j = 0; j < 4; j++) acc[mt][nt][j] = 0.f;

    const __half* Ab = As + (pl * 32 + gid) * KP + 2 * tig;
    const __half* Bb = Bs + (nh + gid) * KP + 2 * tig;

#pragma unroll 1
    for (int ks = 0; ks < CMID / 16; ks++) {
        uint32_t a[2][4];
#pragma unroll
        for (int mt = 0; mt < 2; mt++) {
            const __half* p = Ab + mt * 16 * KP + ks * 16;
            a[mt][0] = *(const uint32_t*)(p);
            a[mt][1] = *(const uint32_t*)(p + 8 * KP);
            a[mt][2] = *(const uint32_t*)(p + 8);
            a[mt][3] = *(const uint32_t*)(p + 8 * KP + 8);
        }
#pragma unroll
        for (int nt = 0; nt < 8; nt++) {
            const __half* p = Bb + nt * 8 * KP + ks * 16;
            uint32_t b[2] = { *(const uint32_t*)(p), *(const uint32_t*)(p + 8) };
            mma16816(acc[0][nt], a[0], b);
            mma16816(acc[1][nt], a[1], b);
        }
    }

    // epilogue: max over 32 neighbor rows then lrelu(max + bias)
    int pglob = p0 + pl;
#pragma unroll
    for (int nt = 0; nt < 8; nt++) {
        float v0 = fmaxf(fmaxf(acc[0][nt][0], acc[0][nt][2]),
                         fmaxf(acc[1][nt][0], acc[1][nt][2]));
        float v1 = fmaxf(fmaxf(acc[0][nt][1], acc[0][nt][3]),
                         fmaxf(acc[1][nt][1], acc[1][nt][3]));
#pragma unroll
        for (int s = 4; s < 32; s <<= 1) {
            v0 = fmaxf(v0, __shfl_xor_sync(0xffffffffu, v0, s));
            v1 = fmaxf(v1, __shfl_xor_sync(0xffffffffu, v1, s));
        }
        if (lane < 4) {
            int col = n0 + nh + nt * 8 + 2 * lane;
            out[(size_t)pglob * COUT + col]     = lrelu(v0 + bb[col]);
            out[(size_t)pglob * COUT + col + 1] = lrelu(v1 + bb[col + 1]);
        }
    }
}

// ---------------- fused head: concat(704) -> 512 -> 256 -> 12 ----------------
// 16 rows per block (grid 1024): wf1/wf2 L2 traffic cut 4x vs 4-row blocks.
__global__ __launch_bounds__(256) void head_fused(const float* __restrict__ wf1,
                                                  const float* __restrict__ bf1,
                                                  const float* __restrict__ wf2,
                                                  const float* __restrict__ bf2,
                                                  const float* __restrict__ wf3,
                                                  const float* __restrict__ bf3,
                                                  float* __restrict__ out) {
    extern __shared__ __align__(16) float hsm[];
    float* ins = hsm;               // [16][704]
    float* h1s = ins + 16 * 704;    // [16][512]
    float* h2s = h1s + 16 * 512;    // [16][256]
    int blk = blockIdx.x;
    int tid = threadIdx.x;

    for (int t = tid; t < 16 * 704; t += 256) {
        int r = t / 704, cm = t - r * 704;
        int row = blk * 16 + r;
        float v;
        if (cm < 64)        v = g_x1[(size_t)row * 64 + cm];
        else if (cm < 192)  v = g_x2[(size_t)row * 128 + (cm - 64)];
        else                v = g_x3[(size_t)row * 512 + (cm - 192)];
        ins[t] = v;
    }
    __syncthreads();
    {   // 704 -> 512 : thread = 2 cols x 16 rows
        int co0 = tid * 2;
        float acc[16][2];
#pragma unroll
        for (int r = 0; r < 16; r++) { acc[r][0] = 0.f; acc[r][1] = 0.f; }
#pragma unroll 1
        for (int cm = 0; cm < 704; cm += 4) {
            float2 w0 = *(const float2*)&wf1[(cm + 0) * 512 + co0];
            float2 w1 = *(const float2*)&wf1[(cm + 1) * 512 + co0];
            float2 w2 = *(const float2*)&wf1[(cm + 2) * 512 + co0];
            float2 w3 = *(const float2*)&wf1[(cm + 3) * 512 + co0];
#pragma unroll
            for (int r = 0; r < 16; r++) {
                float4 hv = *(const float4*)&ins[r * 704 + cm];
                acc[r][0] = fmaf(hv.x, w0.x, acc[r][0]);
                acc[r][1] = fmaf(hv.x, w0.y, acc[r][1]);
                acc[r][0] = fmaf(hv.y, w1.x, acc[r][0]);
                acc[r][1] = fmaf(hv.y, w1.y, acc[r][1]);
                acc[r][0] = fmaf(hv.z, w2.x, acc[r][0]);
                acc[r][1] = fmaf(hv.z, w2.y, acc[r][1]);
                acc[r][0] = fmaf(hv.w, w3.x, acc[r][0]);
                acc[r][1] = fmaf(hv.w, w3.y, acc[r][1]);
            }
        }
        float b0 = bf1[co0], b1 = bf1[co0 + 1];
#pragma unroll
        for (int r = 0; r < 16; r++) {
            h1s[r * 512 + co0]     = lrelu(acc[r][0] + b0);
            h1s[r * 512 + co0 + 1] = lrelu(acc[r][1] + b1);
        }
    }
    __syncthreads();
    {   // 512 -> 256 : thread = 1 col x 16 rows
        int co = tid;
        float acc[16];
#pragma unroll
        for (int r = 0; r < 16; r++) acc[r] = 0.f;
#pragma unroll 1
        for (int cm = 0; cm < 512; cm += 4) {
            float w0 = wf2[(cm + 0) * 256 + co];
            float w1 = wf2[(cm + 1) * 256 + co];
            float w2 = wf2[(cm + 2) * 256 + co];
            float w3 = wf2[(cm + 3) * 256 + co];
#pragma unroll
            for (int r = 0; r < 16; r++) {
                float4 hv = *(const float4*)&h1s[r * 512 + cm];
                acc[r] = fmaf(hv.x, w0, acc[r]);
                acc[r] = fmaf(hv.y, w1, acc[r]);
                acc[r] = fmaf(hv.z, w2, acc[r]);
                acc[r] = fmaf(hv.w, w3, acc[r]);
            }
        }
        float b = bf2[co];
#pragma unroll
        for (int r = 0; r < 16; r++) h2s[r * 256 + co] = lrelu(acc[r] + b);
    }
    __syncthreads();
    if (tid < 192) {   // 256 -> 12 (no lrelu)
        int r = tid / 12, c = tid - r * 12;
        float a0 = bf3[c], a1 = 0.f, a2 = 0.f, a3 = 0.f;
        const float* h = &h2s[r * 256];
#pragma unroll 4
        for (int cm = 0; cm < 256; cm += 4) {
            a0 = fmaf(h[cm + 0], wf3[(cm + 0) * 12 + c], a0);
            a1 = fmaf(h[cm + 1], wf3[(cm + 1) * 12 + c], a1);
            a2 = fmaf(h[cm + 2], wf3[(cm + 2) * 12 + c], a2);
            a3 = fmaf(h[cm + 3], wf3[(cm + 3) * 12 + c], a3);
        }
        out[(size_t)(blk * 16 + r) * 12 + c] = (a0 + a1) + (a2 + a3);
    }
}

// ---------------- launch ----------------
constexpr int SMEM_P1 = (2 * 64 * 4 + 32 * 4 + 64) * 4;            //   2816
constexpr int SMEM_P2 = (2 * 64 * 68 + 32 * 68 + 64) * 4;          //  43776
constexpr int SMEM_P3 = (2 * 128 * 132 + 32 * 132 + 128) * 4;      // 152576
constexpr int SMEM_E1 = (512 * 72 + 64 * 72) * 2 + 512 * 4;        //  84992
constexpr int SMEM_E2 = (256 * 72 + 128 * 72) * 2 + 256 * 4;       //  56320
constexpr int SMEM_E3 = (256 * 136 + 128 * 136) * 2 + 256 * 4;     // 105472
constexpr int SMEM_HD = (16 * 704 + 16 * 512 + 16 * 256) * 4;      //  94208

extern "C" void kernel_launch(void* const* d_in, const int* in_sizes, int n_in,
                              void* d_out, int out_size) {
    const float* x   = (const float*)d_in[0];
    const float* pos = (const float*)d_in[1];
    const float* w1a = (const float*)d_in[2];
    const float* b1a = (const float*)d_in[3];
    const float* w1b = (const float*)d_in[4];
    const float* b1b = (const float*)d_in[5];
    const float* w2a = (const float*)d_in[6];
    const float* b2a = (const float*)d_in[7];
    const float* w2b = (const float*)d_in[8];
    const float* b2b = (const float*)d_in[9];
    const float* w3a = (const float*)d_in[10];
    const float* b3a = (const float*)d_in[11];
    const float* w3b = (const float*)d_in[12];
    const float* b3b = (const float*)d_in[13];
    const float* wf1 = (const float*)d_in[14];
    const float* bf1 = (const float*)d_in[15];
    const float* wf2 = (const float*)d_in[16];
    const float* bf2 = (const float*)d_in[17];
    const float* wf3 = (const float*)d_in[18];
    const float* bf3 = (const float*)d_in[19];
    float* out = (float*)d_out;

    float *x1p, *x2p, *x3p;
    __half *wt1p, *wt2p, *wt3p;
    cudaGetSymbolAddress((void**)&x1p, g_x1);
    cudaGetSymbolAddress((void**)&x2p, g_x2);
    cudaGetSymbolAddress((void**)&x3p, g_x3);
    cudaGetSymbolAddress((void**)&wt1p, g_wbT1);
    cudaGetSymbolAddress((void**)&wt2p, g_wbT2);
    cudaGetSymbolAddress((void**)&wt3p, g_wbT3);

    static bool attr_done = false;
    if (!attr_done) {
        cudaFuncSetAttribute(proj_kernel<128, 128, 132>,
                             cudaFuncAttributeMaxDynamicSharedMemorySize, SMEM_P3);
        cudaFuncSetAttribute(edge_mma<64, 64, 16, 64>,
                             cudaFuncAttributeMaxDynamicSharedMemorySize, SMEM_E1);
        cudaFuncSetAttribute(edge_mma<64, 128, 8, 128>,
                             cudaFuncAttributeMaxDynamicSharedMemorySize, SMEM_E2);
        cudaFuncSetAttribute(edge_mma<128, 512, 8, 128>,
                             cudaFuncAttributeMaxDynamicSharedMemorySize, SMEM_E3);
        cudaFuncSetAttribute(head_fused,
                             cudaFuncAttributeMaxDynamicSharedMemorySize, SMEM_HD);
        attr_done = true;
    }

    // launch order puts knn at slot 6 (ncu -s 5 -c 1 captures it)
    sq_kernel<<<BN_ / 256, 256>>>(pos);                                    // 1
    proj_kernel<3, 64, 4><<<BN_ / 32, 256, SMEM_P1>>>(x, w1a, b1a);        // 2
    prep_wbT<<<16, 256>>>(w1b, wt1p, 64, 64, 0, 4096);                     // 3
    prep_wbT<<<32, 256>>>(w2b, wt2p, 64, 128, 0, 8192);                    // 4
    prep_wbT<<<128, 256>>>(w3b, wt3p, 128, 512, 0, 32768);                 // 5
    knn_kernel<<<BN_, 256>>>(pos);                                         // 6
    prep_wbT<<<128, 256>>>(w3b, wt3p, 128, 512, 32768, 32768);             // 7

    // block1: 3 -> 64 -> 64
    edge_mma<64, 64, 16, 64><<<BN_ / 16, 512, SMEM_E1>>>(wt1p, b1b, x1p);
    // block2: 64 -> 64 -> 128
    proj_kernel<64, 64, 68><<<BN_ / 32, 256, SMEM_P2>>>(x1p, w2a, b2a);
    edge_mma<64, 128, 8, 128><<<BN_ / 8, 512, SMEM_E2>>>(wt2p, b2b, x2p);
    // block3: 128 -> 128 -> 512
    proj_kernel<128, 128, 132><<<BN_ / 32, 256, SMEM_P3>>>(x2p, w3a, b3a);
    edge_mma<128, 512, 8, 128><<<dim3(BN_ / 8, 4), 512, SMEM_E3>>>(wt3p, b3b, x3p);

    // fused head (16 rows/block)
    head_fused<<<BN_ / 16, 256, SMEM_HD>>>(wf1, bf1, wf2, bf2, wf3, bf3, out);
}

// round 8
// speedup vs baseline: 1.6149x; 1.0071x over previous
#include <cuda_runtime.h>
#include <cuda_fp16.h>
#include <cstdint>

// DGCNN: B=8, N=2048, k=32.  (sm_103 PTX target: no tcgen05 -> mma.sync f16)
// knn(sq fused) -> proj1 -> prep -> edge1/2/3 (f16 mma + ldmatrix) -> fused head.
// Edge trick: feat@wa = p[point] + q[neighbor]; per-edge work is
// lrelu(p+q) then CMID x COUT GEMM + max over k (lrelu monotone -> max last).
// R7: fix prep_all coverage (w3b is 65536 elems; R6 converted only half).

#define NEG 0.2f
constexpr int B_  = 8;
constexpr int N_  = 2048;
constexpr int BN_ = B_ * N_;   // 16384
constexpr int K_  = 32;

// ---- scratch (device globals; no runtime allocation allowed) ----
__device__ int    g_idx[BN_ * K_];
__device__ float  g_p[BN_ * 128];
__device__ float  g_q[BN_ * 128];
__device__ float  g_x1[BN_ * 64];
__device__ float  g_x2[BN_ * 128];
__device__ float  g_x3[BN_ * 512];
__device__ __half g_wbT1[64 * 64];     // w1b^T [64][64]
__device__ __half g_wbT2[128 * 64];    // w2b^T [128][64]
__device__ __half g_wbT3[512 * 128];   // w3b^T [512][128]

__device__ __forceinline__ float lrelu(float v) { return v >= 0.f ? v : NEG * v; }

__device__ __forceinline__ uint32_t pack_f16x2(float lo, float hi) {
    uint32_t u;
    asm("cvt.rn.f16x2.f32 %0, %1, %2;" : "=r"(u) : "f"(hi), "f"(lo));
    return u;
}

__device__ __forceinline__ uint32_t smem_u32(const void* p) {
    uint32_t a;
    asm("{ .reg .u64 t; cvta.to.shared.u64 t, %1; cvt.u32.u64 %0, t; }" : "=r"(a) : "l"(p));
    return a;
}

__device__ __forceinline__ void mma16816(float d[4], const uint32_t a[4],
                                         const uint32_t b[2]) {
    asm volatile(
        "mma.sync.aligned.m16n8k16.row.col.f32.f16.f16.f32 "
        "{%0,%1,%2,%3}, {%4,%5,%6,%7}, {%8,%9}, {%0,%1,%2,%3};\n"
        : "+f"(d[0]), "+f"(d[1]), "+f"(d[2]), "+f"(d[3])
        : "r"(a[0]), "r"(a[1]), "r"(a[2]), "r"(a[3]), "r"(b[0]), "r"(b[1]));
}

#define LDSM4(r, addr) \
    asm volatile("ldmatrix.sync.aligned.m8n8.x4.shared.b16 {%0,%1,%2,%3}, [%4];" \
                 : "=r"((r)[0]), "=r"((r)[1]), "=r"((r)[2]), "=r"((r)[3]) \
                 : "r"(addr))

// ---------------- weight transpose + f16 prep (all three, one launch) ---------
// totals: w1b 64*64=4096, w2b 64*128=8192, w3b 128*512=65536  => 77824 threads
__global__ void prep_all(const float* __restrict__ w1, const float* __restrict__ w2,
                         const float* __restrict__ w3, __half* __restrict__ t1,
                         __half* __restrict__ t2, __half* __restrict__ t3) {
    int t = blockIdx.x * 256 + threadIdx.x;
    if (t < 4096) {
        int k = t >> 6, n = t & 63;
        t1[n * 64 + k] = __float2half_rn(w1[t]);
    } else if (t < 12288) {
        int e = t - 4096;
        int k = e >> 7, n = e & 127;
        t2[n * 64 + k] = __float2half_rn(w2[e]);
    } else if (t < 77824) {
        int e = t - 12288;
        int k = e >> 9, n = e & 511;
        t3[n * 128 + k] = __float2half_rn(w3[e]);
    }
}

// ---------------- kNN (sq fused): barrier-light hierarchical selection -------
// Warp w computes 256 distances (8/lane, in registers), selects its top-32 via
// shfl_xor min rounds. Warp 0 merges the 8x32 candidates.
// Key = (ordered(d2) << 32) | idx  ==> asc d2, tie lowest idx (= lax.top_k).
__global__ __launch_bounds__(256) void knn_kernel(const float* __restrict__ pos) {
    __shared__ unsigned long long cand[256];
    int point = blockIdx.x;
    int base  = (point >> 11) * N_;
    int tid   = threadIdx.x;
    int w     = tid >> 5, lane = tid & 31;

    float px = pos[point * 3 + 0], py = pos[point * 3 + 1], pz = pos[point * 3 + 2];
    float sqn = fmaf(pz, pz, fmaf(py, py, px * px));

    unsigned long long k[8];
#pragma unroll
    for (int i = 0; i < 8; i++) {
        int m = (w << 8) + (i << 5) + lane;
        const float* pm = pos + (size_t)(base + m) * 3;
        float mx = pm[0], my = pm[1], mz = pm[2];
        float dot = fmaf(pz, mz, fmaf(py, my, px * mx));
        float sqm = fmaf(mz, mz, fmaf(my, my, mx * mx));
        float d2  = (sqn - 2.f * dot) + sqm;
        unsigned u = __float_as_uint(d2);
        u = (u & 0x80000000u) ? ~u : (u | 0x80000000u);
        k[i] = ((unsigned long long)u << 32) | (unsigned)m;
    }
    unsigned long long lmin = k[0];
#pragma unroll
    for (int i = 1; i < 8; i++) lmin = k[i] < lmin ? k[i] : lmin;

#pragma unroll 1
    for (int it = 0; it < K_; it++) {
        unsigned long long mn = lmin;
#pragma unroll
        for (int off = 16; off; off >>= 1) {
            unsigned long long o = __shfl_xor_sync(0xffffffffu, mn, off);
            mn = o < mn ? o : mn;
        }
        if (lane == 0) cand[(w << 5) + it] = mn;
        if (lmin == mn) {
#pragma unroll
            for (int i = 0; i < 8; i++) if (k[i] == mn) k[i] = ~0ull;
            lmin = k[0];
#pragma unroll
            for (int i = 1; i < 8; i++) lmin = k[i] < lmin ? k[i] : lmin;
        }
    }
    __syncthreads();

    if (w == 0) {
        unsigned long long c[8];
#pragma unroll
        for (int i = 0; i < 8; i++) c[i] = cand[(i << 5) + lane];
        unsigned long long lm = c[0];
#pragma unroll
        for (int i = 1; i < 8; i++) lm = c[i] < lm ? c[i] : lm;
#pragma unroll 1
        for (int it = 0; it < K_; it++) {
            unsigned long long mn = lm;
#pragma unroll
            for (int off = 16; off; off >>= 1) {
                unsigned long long o = __shfl_xor_sync(0xffffffffu, mn, off);
                mn = o < mn ? o : mn;
            }
            if (lane == 0) g_idx[point * K_ + it] = base + (int)(unsigned)mn;
            if (lm == mn) {
#pragma unroll
                for (int i = 0; i < 8; i++) if (c[i] == mn) c[i] = ~0ull;
                lm = c[0];
#pragma unroll
                for (int i = 1; i < 8; i++) lm = c[i] < lm ? c[i] : lm;
            }
        }
    }
}

// ---------------- batched per-point projections p,q ----------------
// 32 points per block; weights staged in smem once.
// p = x @ (wa_top - wa_bot) + ba ; q = x @ wa_bot
template <int CIN, int CMID, int CINP>
__global__ __launch_bounds__(256) void proj_kernel(const float* __restrict__ x,
                                                   const float* __restrict__ wa,
                                                   const float* __restrict__ ba) {
    extern __shared__ __align__(16) float smf[];
    float* wts = smf;                      // [CMID][CINP]
    float* wqs = wts + CMID * CINP;        // [CMID][CINP]
    float* xs  = wqs + CMID * CINP;        // [32][CINP]
    float* bas = xs + 32 * CINP;           // [CMID]
    int tid = threadIdx.x;
    int p0  = blockIdx.x * 32;

    for (int t = tid; t < CIN * CMID; t += 256) {
        int ci = t / CMID, cm = t - ci * CMID;
        float top = wa[t], bot = wa[CIN * CMID + t];
        wts[cm * CINP + ci] = top - bot;
        wqs[cm * CINP + ci] = bot;
    }
    for (int t = tid; t < 32 * CIN; t += 256) {
        int pp = t / CIN, ci = t - pp * CIN;
        xs[pp * CINP + ci] = x[(size_t)(p0 + pp) * CIN + ci];
    }
    if (tid < CMID) bas[tid] = ba[tid];
    __syncthreads();

    constexpr int LANES = 256 / CMID;
    int li = tid / CMID, cm = tid - li * CMID;
    const float* wtr = wts + cm * CINP;
    const float* wqr = wqs + cm * CINP;
    float bias = bas[cm];

    for (int pp = li; pp < 32; pp += LANES) {
        const float* xr = xs + pp * CINP;
        float pa = bias, qa = 0.f;
        if constexpr (CIN % 4 == 0) {
#pragma unroll
            for (int ci = 0; ci < CIN; ci += 4) {
                float4 xv = *(const float4*)(xr + ci);
                float4 wt4 = *(const float4*)(wtr + ci);
                float4 wq4 = *(const float4*)(wqr + ci);
                pa = fmaf(xv.x, wt4.x, pa); qa = fmaf(xv.x, wq4.x, qa);
                pa = fmaf(xv.y, wt4.y, pa); qa = fmaf(xv.y, wq4.y, qa);
                pa = fmaf(xv.z, wt4.z, pa); qa = fmaf(xv.z, wq4.z, qa);
                pa = fmaf(xv.w, wt4.w, pa); qa = fmaf(xv.w, wq4.w, qa);
            }
        } else {
#pragma unroll
            for (int ci = 0; ci < CIN; ci++) {
                float xv = xr[ci];
                pa = fmaf(xv, wtr[ci], pa);
                qa = fmaf(xv, wqr[ci], qa);
            }
        }
        g_p[(size_t)(p0 + pp) * CMID + cm] = pa;
        g_q[(size_t)(p0 + pp) * CMID + cm] = qa;
    }
}

// ---------------- edge blocks via mma.sync m16n8k16 f16 + ldmatrix ------------
// Block: PT points (A = PT*32 edge rows, f16), N-tile NT cols of wbT.
// 512 threads, 16 warps; warp = (point, 64-col group): 2 m16 x 8 n8, K step 16.
// Fragments via LDSM.x4 (6 per k-step, conflict-free at KP=72/136).
// Epilogue: colmax over 32 k-rows in regs+shfl, lrelu(max + bias) (monotone).
template <int CMID, int COUT, int PT, int NT>
__global__ __launch_bounds__(512) void edge_mma(const __half* __restrict__ wbT,
                                                const float* __restrict__ bb,
                                                float* __restrict__ out) {
    constexpr int KP    = CMID + 8;        // halves; stride 2*KP bytes, LDSM-safe
    constexpr int AROWS = PT * 32;
    constexpr int CPR8  = CMID / 8;        // 8-half chunks per row
    extern __shared__ __align__(16) char smraw[];
    __half* As = (__half*)smraw;                    // [AROWS][KP]
    __half* Bs = As + AROWS * KP;                   // [NT][KP]
    int*  nidx = (int*)(Bs + NT * KP);              // [AROWS]

    int tid = threadIdx.x, w = tid >> 5, lane = tid & 31;
    int p0 = blockIdx.x * PT, n0 = blockIdx.y * NT;

    for (int t = tid; t < AROWS; t += 512) nidx[t] = g_idx[p0 * K_ + t];
    __syncthreads();

    // A fill: row r=(pt,nbr): lrelu(p + q[nb]) -> f16
#pragma unroll
    for (int i = 0; i < AROWS * CPR8 / 512; i++) {
        int e  = i * 512 + tid;
        int r  = e / CPR8;
        int c0 = (e - r * CPR8) * 8;
        const float* qr = g_q + (size_t)nidx[r] * CMID + c0;
        const float* pr = g_p + (size_t)(p0 + (r >> 5)) * CMID + c0;
        float4 qa = *(const float4*)qr, qb = *(const float4*)(qr + 4);
        float4 pa = *(const float4*)pr, pb = *(const float4*)(pr + 4);
        uint4 pk = { pack_f16x2(lrelu(pa.x + qa.x), lrelu(pa.y + qa.y)),
                     pack_f16x2(lrelu(pa.z + qa.z), lrelu(pa.w + qa.w)),
                     pack_f16x2(lrelu(pb.x + qb.x), lrelu(pb.y + qb.y)),
                     pack_f16x2(lrelu(pb.z + qb.z), lrelu(pb.w + qb.w)) };
        *(uint4*)(As + r * KP + c0) = pk;
    }
    // B fill: Bs[n][k] from f16 wbT[COUT][CMID]
#pragma unroll
    for (int i = 0; i < NT * CPR8 / 512; i++) {
        int e  = i * 512 + tid;
        int r  = e / CPR8;
        int c0 = (e - r * CPR8) * 8;
        *(uint4*)(Bs + r * KP + c0) =
            *(const uint4*)(wbT + (size_t)(n0 + r) * CMID + c0);
    }
    __syncthreads();

    constexpr int NHW = NT / 64;
    int pl = w / NHW;
    int nh = (w % NHW) * 64;

    float acc[2][8][4];
#pragma unroll
    for (int mt = 0; mt < 2; mt++)
#pragma unroll
        for (int nt = 0; nt < 8; nt++)
#pragma unroll
            for (int j = 0; j < 4; j++) acc[mt][nt][j] = 0.f;

    // ldmatrix per-lane addresses
    // A x4: tiles {m0..7,k0}{m8..15,k0}{m0..7,k8}{m8..15,k8}
    uint32_t aBase = smem_u32(As) +
        (uint32_t)(((pl * 32 + (lane & 15)) * KP + (lane >> 4) * 8) * 2);
    // B x4 (2 n-tiles): tiles {n0..7,k0}{n0..7,k8}{n8..15,k0}{n8..15,k8}
    uint32_t bBase = smem_u32(Bs) +
        (uint32_t)(((nh + (lane & 7) + (lane >> 4) * 8) * KP + ((lane >> 3) & 1) * 8) * 2);

#pragma unroll 1
    for (int ks = 0; ks < CMID / 16; ks++) {
        uint32_t a0[4], a1[4];
        LDSM4(a0, aBase + ks * 32);
        LDSM4(a1, aBase + 16 * KP * 2 + ks * 32);
#pragma unroll
        for (int ntp = 0; ntp < 4; ntp++) {
            uint32_t b[4];
            LDSM4(b, bBase + ntp * (16 * KP * 2) + ks * 32);
            mma16816(acc[0][2 * ntp],     a0, b + 0);
            mma16816(acc[1][2 * ntp],     a1, b + 0);
            mma16816(acc[0][2 * ntp + 1], a0, b + 2);
            mma16816(acc[1][2 * ntp + 1], a1, b + 2);
        }
    }

    // epilogue: max over 32 neighbor rows then lrelu(max + bias)
    int pglob = p0 + pl;
#pragma unroll
    for (int nt = 0; nt < 8; nt++) {
        float v0 = fmaxf(fmaxf(acc[0][nt][0], acc[0][nt][2]),
                         fmaxf(acc[1][nt][0], acc[1][nt][2]));
        float v1 = fmaxf(fmaxf(acc[0][nt][1], acc[0][nt][3]),
                         fmaxf(acc[1][nt][1], acc[1][nt][3]));
#pragma unroll
        for (int s = 4; s < 32; s <<= 1) {
            v0 = fmaxf(v0, __shfl_xor_sync(0xffffffffu, v0, s));
            v1 = fmaxf(v1, __shfl_xor_sync(0xffffffffu, v1, s));
        }
        if (lane < 4) {
            int col = n0 + nh + nt * 8 + 2 * lane;
            out[(size_t)pglob * COUT + col]     = lrelu(v0 + bb[col]);
            out[(size_t)pglob * COUT + col + 1] = lrelu(v1 + bb[col + 1]);
        }
    }
}

// ---------------- fused head: concat(704) -> 512 -> 256 -> 12 ----------------
// 16 rows per block (grid 1024).
__global__ __launch_bounds__(256) void head_fused(const float* __restrict__ wf1,
                                                  const float* __restrict__ bf1,
                                                  const float* __restrict__ wf2,
                                                  const float* __restrict__ bf2,
                                                  const float* __restrict__ wf3,
                                                  const float* __restrict__ bf3,
                                                  float* __restrict__ out) {
    extern __shared__ __align__(16) float hsm[];
    float* ins = hsm;               // [16][704]
    float* h1s = ins + 16 * 704;    // [16][512]
    float* h2s = h1s + 16 * 512;    // [16][256]
    int blk = blockIdx.x;
    int tid = threadIdx.x;

    for (int t = tid; t < 16 * 704; t += 256) {
        int r = t / 704, cm = t - r * 704;
        int row = blk * 16 + r;
        float v;
        if (cm < 64)        v = g_x1[(size_t)row * 64 + cm];
        else if (cm < 192)  v = g_x2[(size_t)row * 128 + (cm - 64)];
        else                v = g_x3[(size_t)row * 512 + (cm - 192)];
        ins[t] = v;
    }
    __syncthreads();
    {   // 704 -> 512 : thread = 2 cols x 16 rows
        int co0 = tid * 2;
        float acc[16][2];
#pragma unroll
        for (int r = 0; r < 16; r++) { acc[r][0] = 0.f; acc[r][1] = 0.f; }
#pragma unroll 1
        for (int cm = 0; cm < 704; cm += 4) {
            float2 w0 = *(const float2*)&wf1[(cm + 0) * 512 + co0];
            float2 w1 = *(const float2*)&wf1[(cm + 1) * 512 + co0];
            float2 w2 = *(const float2*)&wf1[(cm + 2) * 512 + co0];
            float2 w3 = *(const float2*)&wf1[(cm + 3) * 512 + co0];
#pragma unroll
            for (int r = 0; r < 16; r++) {
                float4 hv = *(const float4*)&ins[r * 704 + cm];
                acc[r][0] = fmaf(hv.x, w0.x, acc[r][0]);
                acc[r][1] = fmaf(hv.x, w0.y, acc[r][1]);
                acc[r][0] = fmaf(hv.y, w1.x, acc[r][0]);
                acc[r][1] = fmaf(hv.y, w1.y, acc[r][1]);
                acc[r][0] = fmaf(hv.z, w2.x, acc[r][0]);
                acc[r][1] = fmaf(hv.z, w2.y, acc[r][1]);
                acc[r][0] = fmaf(hv.w, w3.x, acc[r][0]);
                acc[r][1] = fmaf(hv.w, w3.y, acc[r][1]);
            }
        }
        float b0 = bf1[co0], b1 = bf1[co0 + 1];
#pragma unroll
        for (int r = 0; r < 16; r++) {
            h1s[r * 512 + co0]     = lrelu(acc[r][0] + b0);
            h1s[r * 512 + co0 + 1] = lrelu(acc[r][1] + b1);
        }
    }
    __syncthreads();
    {   // 512 -> 256 : thread = 1 col x 16 rows
        int co = tid;
        float acc[16];
#pragma unroll
        for (int r = 0; r < 16; r++) acc[r] = 0.f;
#pragma unroll 1
        for (int cm = 0; cm < 512; cm += 4) {
            float w0 = wf2[(cm + 0) * 256 + co];
            float w1 = wf2[(cm + 1) * 256 + co];
            float w2 = wf2[(cm + 2) * 256 + co];
            float w3 = wf2[(cm + 3) * 256 + co];
#pragma unroll
            for (int r = 0; r < 16; r++) {
                float4 hv = *(const float4*)&h1s[r * 512 + cm];
                acc[r] = fmaf(hv.x, w0, acc[r]);
                acc[r] = fmaf(hv.y, w1, acc[r]);
                acc[r] = fmaf(hv.z, w2, acc[r]);
                acc[r] = fmaf(hv.w, w3, acc[r]);
            }
        }
        float b = bf2[co];
#pragma unroll
        for (int r = 0; r < 16; r++) h2s[r * 256 + co] = lrelu(acc[r] + b);
    }
    __syncthreads();
    if (tid < 192) {   // 256 -> 12 (no lrelu)
        int r = tid / 12, c = tid - r * 12;
        float a0 = bf3[c], a1 = 0.f, a2 = 0.f, a3 = 0.f;
        const float* h = &h2s[r * 256];
#pragma unroll 4
        for (int cm = 0; cm < 256; cm += 4) {
            a0 = fmaf(h[cm + 0], wf3[(cm + 0) * 12 + c], a0);
            a1 = fmaf(h[cm + 1], wf3[(cm + 1) * 12 + c], a1);
            a2 = fmaf(h[cm + 2], wf3[(cm + 2) * 12 + c], a2);
            a3 = fmaf(h[cm + 3], wf3[(cm + 3) * 12 + c], a3);
        }
        out[(size_t)(blk * 16 + r) * 12 + c] = (a0 + a1) + (a2 + a3);
    }
}

// ---------------- launch ----------------
constexpr int SMEM_P1 = (2 * 64 * 4 + 32 * 4 + 64) * 4;            //   2816
constexpr int SMEM_P2 = (2 * 64 * 68 + 32 * 68 + 64) * 4;          //  43776
constexpr int SMEM_P3 = (2 * 128 * 132 + 32 * 132 + 128) * 4;      // 152576
constexpr int SMEM_E1 = (512 * 72 + 64 * 72) * 2 + 512 * 4;        //  84992
constexpr int SMEM_E2 = (256 * 72 + 128 * 72) * 2 + 256 * 4;       //  56320
constexpr int SMEM_E3 = (256 * 136 + 128 * 136) * 2 + 256 * 4;     // 105472
constexpr int SMEM_HD = (16 * 704 + 16 * 512 + 16 * 256) * 4;      //  94208

extern "C" void kernel_launch(void* const* d_in, const int* in_sizes, int n_in,
                              void* d_out, int out_size) {
    const float* x   = (const float*)d_in[0];
    const float* pos = (const float*)d_in[1];
    const float* w1a = (const float*)d_in[2];
    const float* b1a = (const float*)d_in[3];
    const float* w1b = (const float*)d_in[4];
    const float* b1b = (const float*)d_in[5];
    const float* w2a = (const float*)d_in[6];
    const float* b2a = (const float*)d_in[7];
    const float* w2b = (const float*)d_in[8];
    const float* b2b = (const float*)d_in[9];
    const float* w3a = (const float*)d_in[10];
    const float* b3a = (const float*)d_in[11];
    const float* w3b = (const float*)d_in[12];
    const float* b3b = (const float*)d_in[13];
    const float* wf1 = (const float*)d_in[14];
    const float* bf1 = (const float*)d_in[15];
    const float* wf2 = (const float*)d_in[16];
    const float* bf2 = (const float*)d_in[17];
    const float* wf3 = (const float*)d_in[18];
    const float* bf3 = (const float*)d_in[19];
    float* out = (float*)d_out;

    float *x1p, *x2p, *x3p;
    __half *wt1p, *wt2p, *wt3p;
    cudaGetSymbolAddress((void**)&x1p, g_x1);
    cudaGetSymbolAddress((void**)&x2p, g_x2);
    cudaGetSymbolAddress((void**)&x3p, g_x3);
    cudaGetSymbolAddress((void**)&wt1p, g_wbT1);
    cudaGetSymbolAddress((void**)&wt2p, g_wbT2);
    cudaGetSymbolAddress((void**)&wt3p, g_wbT3);

    static bool attr_done = false;
    if (!attr_done) {
        cudaFuncSetAttribute(proj_kernel<128, 128, 132>,
                             cudaFuncAttributeMaxDynamicSharedMemorySize, SMEM_P3);
        cudaFuncSetAttribute(edge_mma<64, 64, 16, 64>,
                             cudaFuncAttributeMaxDynamicSharedMemorySize, SMEM_E1);
        cudaFuncSetAttribute(edge_mma<64, 128, 8, 128>,
                             cudaFuncAttributeMaxDynamicSharedMemorySize, SMEM_E2);
        cudaFuncSetAttribute(edge_mma<128, 512, 8, 128>,
                             cudaFuncAttributeMaxDynamicSharedMemorySize, SMEM_E3);
        cudaFuncSetAttribute(head_fused,
                             cudaFuncAttributeMaxDynamicSharedMemorySize, SMEM_HD);
        attr_done = true;
    }

    // launch order puts edge1 at slot 4 (the slot ncu empirically captures)
    knn_kernel<<<BN_, 256>>>(pos);                                         // 1
    proj_kernel<3, 64, 4><<<BN_ / 32, 256, SMEM_P1>>>(x, w1a, b1a);        // 2
    prep_all<<<304, 256>>>(w1b, w2b, w3b, wt1p, wt2p, wt3p);               // 3

    // block1: 3 -> 64 -> 64
    edge_mma<64, 64, 16, 64><<<BN_ / 16, 512, SMEM_E1>>>(wt1p, b1b, x1p);  // 4 <- ncu
    // block2: 64 -> 64 -> 128
    proj_kernel<64, 64, 68><<<BN_ / 32, 256, SMEM_P2>>>(x1p, w2a, b2a);
    edge_mma<64, 128, 8, 128><<<BN_ / 8, 512, SMEM_E2>>>(wt2p, b2b, x2p);
    // block3: 128 -> 128 -> 512
    proj_kernel<128, 128, 132><<<BN_ / 32, 256, SMEM_P3>>>(x2p, w3a, b3a);
    edge_mma<128, 512, 8, 128><<<dim3(BN_ / 8, 4), 512, SMEM_E3>>>(wt3p, b3b, x3p);

    // fused head (16 rows/block)
    head_fused<<<BN_ / 16, 256, SMEM_HD>>>(wf1, bf1, wf2, bf2, wf3, bf3, out);
}

// round 9
// speedup vs baseline: 2.3565x; 1.4592x over previous
#include <cuda_runtime.h>
#include <cuda_fp16.h>
#include <cstdint>

// DGCNN: B=8, N=2048, k=32.  (sm_103 PTX target -> mma.sync f16 + ldmatrix)
// proj1 -> prep_wb -> prep_wf -> knn -> edge1/2/3 (f16 mma) -> head1/2 (f16 mma) -> head3.
// Edge trick: feat@wa = p[point] + q[neighbor]; per-edge work is
// lrelu(p+q) then CMID x COUT GEMM + max over k (lrelu monotone -> max last).
// R9: edges 256thr x 2 blocks/SM + internal n-loop (A gathered once);
//     head1/head2 as f16 mma GEMMs (h1 f16, h2 fp32).

#define NEG 0.2f
constexpr int B_  = 8;
constexpr int N_  = 2048;
constexpr int BN_ = B_ * N_;   // 16384
constexpr int K_  = 32;

// ---- scratch (device globals; no runtime allocation allowed) ----
__device__ int    g_idx[BN_ * K_];
__device__ float  g_p[BN_ * 128];
__device__ float  g_q[BN_ * 128];
__device__ float  g_x1[BN_ * 64];
__device__ float  g_x2[BN_ * 128];
__device__ float  g_x3[BN_ * 512];
__device__ __half g_h1[BN_ * 512];
__device__ float  g_h2[BN_ * 256];
__device__ __half g_wbT1[64 * 64];     // w1b^T [64][64]
__device__ __half g_wbT2[128 * 64];    // w2b^T [128][64]
__device__ __half g_wbT3[512 * 128];   // w3b^T [512][128]
__device__ __half g_wf1T[512 * 704];   // wf1^T [512][704]
__device__ __half g_wf2T[256 * 512];   // wf2^T [256][512]

__device__ __forceinline__ float lrelu(float v) { return v >= 0.f ? v : NEG * v; }

__device__ __forceinline__ uint32_t pack_f16x2(float lo, float hi) {
    uint32_t u;
    asm("cvt.rn.f16x2.f32 %0, %1, %2;" : "=r"(u) : "f"(hi), "f"(lo));
    return u;
}

__device__ __forceinline__ uint32_t smem_u32(const void* p) {
    uint32_t a;
    asm("{ .reg .u64 t; cvta.to.shared.u64 t, %1; cvt.u32.u64 %0, t; }" : "=r"(a) : "l"(p));
    return a;
}

__device__ __forceinline__ void mma16816(float d[4], const uint32_t a[4],
                                         const uint32_t b[2]) {
    asm volatile(
        "mma.sync.aligned.m16n8k16.row.col.f32.f16.f16.f32 "
        "{%0,%1,%2,%3}, {%4,%5,%6,%7}, {%8,%9}, {%0,%1,%2,%3};\n"
        : "+f"(d[0]), "+f"(d[1]), "+f"(d[2]), "+f"(d[3])
        : "r"(a[0]), "r"(a[1]), "r"(a[2]), "r"(a[3]), "r"(b[0]), "r"(b[1]));
}

#define LDSM4(r, addr) \
    asm volatile("ldmatrix.sync.aligned.m8n8.x4.shared.b16 {%0,%1,%2,%3}, [%4];" \
                 : "=r"((r)[0]), "=r"((r)[1]), "=r"((r)[2]), "=r"((r)[3]) \
                 : "r"(addr))

// ---------------- edge-weight transpose + f16 (4096 + 8192 + 65536 = 77824) ---
__global__ void prep_wb(const float* __restrict__ w1, const float* __restrict__ w2,
                        const float* __restrict__ w3, __half* __restrict__ t1,
                        __half* __restrict__ t2, __half* __restrict__ t3) {
    int t = blockIdx.x * 256 + threadIdx.x;
    if (t < 4096) {
        int k = t >> 6, n = t & 63;
        t1[n * 64 + k] = __float2half_rn(w1[t]);
    } else if (t < 12288) {
        int e = t - 4096;
        int k = e >> 7, n = e & 127;
        t2[n * 64 + k] = __float2half_rn(w2[e]);
    } else if (t < 77824) {
        int e = t - 12288;
        int k = e >> 9, n = e & 511;
        t3[n * 128 + k] = __float2half_rn(w3[e]);
    }
}

// ---------------- head-weight transpose + f16 (360448 + 131072 = 491520) ------
__global__ void prep_wf(const float* __restrict__ wf1, const float* __restrict__ wf2,
                        __half* __restrict__ t1, __half* __restrict__ t2) {
    int t = blockIdx.x * 256 + threadIdx.x;
    if (t < 360448) {            // out-indexed: n = t/704, k = t%704
        int n = t / 704, k = t - n * 704;
        t1[t] = __float2half_rn(wf1[k * 512 + n]);
    } else {
        int e = t - 360448;
        int n = e >> 9, k = e & 511;
        t2[e] = __float2half_rn(wf2[k * 256 + n]);
    }
}

// ---------------- kNN (sq fused): barrier-light hierarchical selection -------
__global__ __launch_bounds__(256) void knn_kernel(const float* __restrict__ pos) {
    __shared__ unsigned long long cand[256];
    int point = blockIdx.x;
    int base  = (point >> 11) * N_;
    int tid   = threadIdx.x;
    int w     = tid >> 5, lane = tid & 31;

    float px = pos[point * 3 + 0], py = pos[point * 3 + 1], pz = pos[point * 3 + 2];
    float sqn = fmaf(pz, pz, fmaf(py, py, px * px));

    unsigned long long k[8];
#pragma unroll
    for (int i = 0; i < 8; i++) {
        int m = (w << 8) + (i << 5) + lane;
        const float* pm = pos + (size_t)(base + m) * 3;
        float mx = pm[0], my = pm[1], mz = pm[2];
        float dot = fmaf(pz, mz, fmaf(py, my, px * mx));
        float sqm = fmaf(mz, mz, fmaf(my, my, mx * mx));
        float d2  = (sqn - 2.f * dot) + sqm;
        unsigned u = __float_as_uint(d2);
        u = (u & 0x80000000u) ? ~u : (u | 0x80000000u);
        k[i] = ((unsigned long long)u << 32) | (unsigned)m;
    }
    unsigned long long lmin = k[0];
#pragma unroll
    for (int i = 1; i < 8; i++) lmin = k[i] < lmin ? k[i] : lmin;

#pragma unroll 1
    for (int it = 0; it < K_; it++) {
        unsigned long long mn = lmin;
#pragma unroll
        for (int off = 16; off; off >>= 1) {
            unsigned long long o = __shfl_xor_sync(0xffffffffu, mn, off);
            mn = o < mn ? o : mn;
        }
        if (lane == 0) cand[(w << 5) + it] = mn;
        if (lmin == mn) {
#pragma unroll
            for (int i = 0; i < 8; i++) if (k[i] == mn) k[i] = ~0ull;
            lmin = k[0];
#pragma unroll
            for (int i = 1; i < 8; i++) lmin = k[i] < lmin ? k[i] : lmin;
        }
    }
    __syncthreads();

    if (w == 0) {
        unsigned long long c[8];
#pragma unroll
        for (int i = 0; i < 8; i++) c[i] = cand[(i << 5) + lane];
        unsigned long long lm = c[0];
#pragma unroll
        for (int i = 1; i < 8; i++) lm = c[i] < lm ? c[i] : lm;
#pragma unroll 1
        for (int it = 0; it < K_; it++) {
            unsigned long long mn = lm;
#pragma unroll
            for (int off = 16; off; off >>= 1) {
                unsigned long long o = __shfl_xor_sync(0xffffffffu, mn, off);
                mn = o < mn ? o : mn;
            }
            if (lane == 0) g_idx[point * K_ + it] = base + (int)(unsigned)mn;
            if (lm == mn) {
#pragma unroll
                for (int i = 0; i < 8; i++) if (c[i] == mn) c[i] = ~0ull;
                lm = c[0];
#pragma unroll
                for (int i = 1; i < 8; i++) lm = c[i] < lm ? c[i] : lm;
            }
        }
    }
}

// ---------------- batched per-point projections p,q ----------------
// 32 points per block; weights staged in smem once.
template <int CIN, int CMID, int CINP>
__global__ __launch_bounds__(256) void proj_kernel(const float* __restrict__ x,
                                                   const float* __restrict__ wa,
                                                   const float* __restrict__ ba) {
    extern __shared__ __align__(16) float smf[];
    float* wts = smf;                      // [CMID][CINP]
    float* wqs = wts + CMID * CINP;        // [CMID][CINP]
    float* xs  = wqs + CMID * CINP;        // [32][CINP]
    float* bas = xs + 32 * CINP;           // [CMID]
    int tid = threadIdx.x;
    int p0  = blockIdx.x * 32;

    for (int t = tid; t < CIN * CMID; t += 256) {
        int ci = t / CMID, cm = t - ci * CMID;
        float top = wa[t], bot = wa[CIN * CMID + t];
        wts[cm * CINP + ci] = top - bot;
        wqs[cm * CINP + ci] = bot;
    }
    for (int t = tid; t < 32 * CIN; t += 256) {
        int pp = t / CIN, ci = t - pp * CIN;
        xs[pp * CINP + ci] = x[(size_t)(p0 + pp) * CIN + ci];
    }
    if (tid < CMID) bas[tid] = ba[tid];
    __syncthreads();

    constexpr int LANES = 256 / CMID;
    int li = tid / CMID, cm = tid - li * CMID;
    const float* wtr = wts + cm * CINP;
    const float* wqr = wqs + cm * CINP;
    float bias = bas[cm];

    for (int pp = li; pp < 32; pp += LANES) {
        const float* xr = xs + pp * CINP;
        float pa = bias, qa = 0.f;
        if constexpr (CIN % 4 == 0) {
#pragma unroll
            for (int ci = 0; ci < CIN; ci += 4) {
                float4 xv = *(const float4*)(xr + ci);
                float4 wt4 = *(const float4*)(wtr + ci);
                float4 wq4 = *(const float4*)(wqr + ci);
                pa = fmaf(xv.x, wt4.x, pa); qa = fmaf(xv.x, wq4.x, qa);
                pa = fmaf(xv.y, wt4.y, pa); qa = fmaf(xv.y, wq4.y, qa);
                pa = fmaf(xv.z, wt4.z, pa); qa = fmaf(xv.z, wq4.z, qa);
                pa = fmaf(xv.w, wt4.w, pa); qa = fmaf(xv.w, wq4.w, qa);
            }
        } else {
#pragma unroll
            for (int ci = 0; ci < CIN; ci++) {
                float xv = xr[ci];
                pa = fmaf(xv, wtr[ci], pa);
                qa = fmaf(xv, wqr[ci], qa);
            }
        }
        g_p[(size_t)(p0 + pp) * CMID + cm] = pa;
        g_q[(size_t)(p0 + pp) * CMID + cm] = qa;
    }
}

// ---------------- edge blocks: f16 mma + ldmatrix, 256 thr, 2 blocks/SM -------
// Block: 8 points (A = 256 edge rows loaded ONCE), loops NITER n-slices of 64.
// 8 warps; warp = point: 2 m16 x 8 n8 per slice, K step 16 via LDSM.x4.
// Epilogue: colmax over 32 k-rows (regs+shfl), lrelu(max + bias) (monotone).
template <int CMID, int COUT, int NITER>
__global__ __launch_bounds__(256, 2) void edge_mma(const __half* __restrict__ wbT,
                                                   const float* __restrict__ bb,
                                                   float* __restrict__ out) {
    constexpr int PT    = 8;
    constexpr int NT    = 64;
    constexpr int KP    = CMID + 8;
    constexpr int AROWS = PT * 32;         // 256
    constexpr int CPR8  = CMID / 8;
    extern __shared__ __align__(16) char smraw[];
    __half* As = (__half*)smraw;                    // [256][KP]
    __half* Bs = As + AROWS * KP;                   // [64][KP]
    int*  nidx = (int*)(Bs + NT * KP);              // [256]

    int tid = threadIdx.x, w = tid >> 5, lane = tid & 31;
    int p0 = blockIdx.x * PT;

    nidx[tid] = g_idx[p0 * K_ + tid];
    __syncthreads();

    // A fill (once): row r=(pt,nbr): lrelu(p + q[nb]) -> f16
#pragma unroll
    for (int i = 0; i < AROWS * CPR8 / 256; i++) {
        int e  = i * 256 + tid;
        int r  = e / CPR8;
        int c0 = (e - r * CPR8) * 8;
        const float* qr = g_q + (size_t)nidx[r] * CMID + c0;
        const float* pr = g_p + (size_t)(p0 + (r >> 5)) * CMID + c0;
        float4 qa = *(const float4*)qr, qb = *(const float4*)(qr + 4);
        float4 pa = *(const float4*)pr, pb = *(const float4*)(pr + 4);
        uint4 pk = { pack_f16x2(lrelu(pa.x + qa.x), lrelu(pa.y + qa.y)),
                     pack_f16x2(lrelu(pa.z + qa.z), lrelu(pa.w + qa.w)),
                     pack_f16x2(lrelu(pb.x + qb.x), lrelu(pb.y + qb.y)),
                     pack_f16x2(lrelu(pb.z + qb.z), lrelu(pb.w + qb.w)) };
        *(uint4*)(As + r * KP + c0) = pk;
    }

    uint32_t aBase = smem_u32(As) +
        (uint32_t)(((w * 32 + (lane & 15)) * KP + (lane >> 4) * 8) * 2);
    uint32_t bBase = smem_u32(Bs) +
        (uint32_t)((((lane & 7) + ((lane >> 4) << 3)) * KP + ((lane >> 3) & 1) * 8) * 2);
    int pglob = p0 + w;

#pragma unroll 1
    for (int it = 0; it < NITER; it++) {
        int n0 = it * NT;
        __syncthreads();   // A ready (it==0) / prior compute done before Bs overwrite
        // B fill: Bs[n][k] from wbT slice
#pragma unroll
        for (int i = 0; i < NT * CPR8 / 256; i++) {
            int e  = i * 256 + tid;
            int r  = e / CPR8;
            int c0 = (e - r * CPR8) * 8;
            *(uint4*)(Bs + r * KP + c0) =
                *(const uint4*)(wbT + (size_t)(n0 + r) * CMID + c0);
        }
        __syncthreads();

        float acc[2][8][4];
#pragma unroll
        for (int mt = 0; mt < 2; mt++)
#pragma unroll
            for (int nt = 0; nt < 8; nt++)
#pragma unroll
                for (int j = 0; j < 4; j++) acc[mt][nt][j] = 0.f;

#pragma unroll 1
        for (int ks = 0; ks < CMID / 16; ks++) {
            uint32_t a0[4], a1[4];
            LDSM4(a0, aBase + ks * 32);
            LDSM4(a1, aBase + 16 * KP * 2 + ks * 32);
#pragma unroll
            for (int ntp = 0; ntp < 4; ntp++) {
                uint32_t b[4];
                LDSM4(b, bBase + ntp * (16 * KP * 2) + ks * 32);
                mma16816(acc[0][2 * ntp],     a0, b + 0);
                mma16816(acc[1][2 * ntp],     a1, b + 0);
                mma16816(acc[0][2 * ntp + 1], a0, b + 2);
                mma16816(acc[1][2 * ntp + 1], a1, b + 2);
            }
        }

        // epilogue: max over 32 neighbor rows then lrelu(max + bias)
#pragma unroll
        for (int nt = 0; nt < 8; nt++) {
            float v0 = fmaxf(fmaxf(acc[0][nt][0], acc[0][nt][2]),
                             fmaxf(acc[1][nt][0], acc[1][nt][2]));
            float v1 = fmaxf(fmaxf(acc[0][nt][1], acc[0][nt][3]),
                             fmaxf(acc[1][nt][1], acc[1][nt][3]));
#pragma unroll
            for (int s = 4; s < 32; s <<= 1) {
                v0 = fmaxf(v0, __shfl_xor_sync(0xffffffffu, v0, s));
                v1 = fmaxf(v1, __shfl_xor_sync(0xffffffffu, v1, s));
            }
            if (lane < 4) {
                int col = n0 + nt * 8 + 2 * lane;
                out[(size_t)pglob * COUT + col]     = lrelu(v0 + bb[col]);
                out[(size_t)pglob * COUT + col + 1] = lrelu(v1 + bb[col + 1]);
            }
        }
    }
}

// ---------------- head1: concat(704) -> 512 via f16 mma, lrelu, h1 f16 --------
// Block: 64 rows x 128 cols, 256 thr, 8 warps = 4 m16-tiles x 2 n64-groups.
// K chunks of 64 staged in smem (A: concat gather -> f16; B: wf1T f16).
__global__ __launch_bounds__(256, 2) void head1_mma(const __half* __restrict__ wT,
                                                    const float* __restrict__ bias) {
    __shared__ __align__(16) __half As[64 * 72];
    __shared__ __align__(16) __half Bs[128 * 72];
    int tid = threadIdx.x, w = tid >> 5, lane = tid & 31;
    int m0 = blockIdx.x * 64, n0 = blockIdx.y * 128;
    int mt = (w >> 1) * 16, ng = (w & 1) * 64;

    float acc[8][4];
#pragma unroll
    for (int nt = 0; nt < 8; nt++)
#pragma unroll
        for (int j = 0; j < 4; j++) acc[nt][j] = 0.f;

    uint32_t aBase = smem_u32(As) +
        (uint32_t)(((mt + (lane & 15)) * 72 + (lane >> 4) * 8) * 2);
    uint32_t bBase = smem_u32(Bs) +
        (uint32_t)(((ng + (lane & 7) + ((lane >> 4) << 3)) * 72 + ((lane >> 3) & 1) * 8) * 2);

#pragma unroll 1
    for (int kc = 0; kc < 11; kc++) {
        const float* src; int stride, off;
        if (kc == 0)      { src = g_x1; stride = 64;  off = 0; }
        else if (kc <= 2) { src = g_x2; stride = 128; off = (kc - 1) * 64; }
        else              { src = g_x3; stride = 512; off = (kc - 3) * 64; }
#pragma unroll
        for (int i = 0; i < 2; i++) {
            int t = i * 256 + tid;
            int r = t >> 3, c0 = (t & 7) * 8;
            const float* sp = src + (size_t)(m0 + r) * stride + off + c0;
            float4 a = *(const float4*)sp, b = *(const float4*)(sp + 4);
            uint4 pk = { pack_f16x2(a.x, a.y), pack_f16x2(a.z, a.w),
                         pack_f16x2(b.x, b.y), pack_f16x2(b.z, b.w) };
            *(uint4*)(As + r * 72 + c0) = pk;
        }
#pragma unroll
        for (int i = 0; i < 4; i++) {
            int t = i * 256 + tid;
            int r = t >> 3, c0 = (t & 7) * 8;
            *(uint4*)(Bs + r * 72 + c0) =
                *(const uint4*)(wT + (size_t)(n0 + r) * 704 + kc * 64 + c0);
        }
        __syncthreads();
#pragma unroll
        for (int ks = 0; ks < 4; ks++) {
            uint32_t a[4];
            LDSM4(a, aBase + ks * 32);
#pragma unroll
            for (int ntp = 0; ntp < 4; ntp++) {
                uint32_t b[4];
                LDSM4(b, bBase + ntp * (16 * 72 * 2) + ks * 32);
                mma16816(acc[2 * ntp],     a, b + 0);
                mma16816(acc[2 * ntp + 1], a, b + 2);
            }
        }
        __syncthreads();
    }

    int gid = lane >> 2, tig = lane & 3;
    int row = m0 + mt + gid;
#pragma unroll
    for (int nt = 0; nt < 8; nt++) {
        int col = n0 + ng + nt * 8 + 2 * tig;
        float b0 = bias[col], b1 = bias[col + 1];
        *(uint32_t*)(g_h1 + (size_t)row * 512 + col) =
            pack_f16x2(lrelu(acc[nt][0] + b0), lrelu(acc[nt][1] + b1));
        *(uint32_t*)(g_h1 + (size_t)(row + 8) * 512 + col) =
            pack_f16x2(lrelu(acc[nt][2] + b0), lrelu(acc[nt][3] + b1));
    }
}

// ---------------- head2: 512 -> 256 via f16 mma, lrelu, h2 fp32 ---------------
__global__ __launch_bounds__(256, 2) void head2_mma(const __half* __restrict__ wT,
                                                    const float* __restrict__ bias) {
    __shared__ __align__(16) __half As[64 * 72];
    __shared__ __align__(16) __half Bs[128 * 72];
    int tid = threadIdx.x, w = tid >> 5, lane = tid & 31;
    int m0 = blockIdx.x * 64, n0 = blockIdx.y * 128;
    int mt = (w >> 1) * 16, ng = (w & 1) * 64;

    float acc[8][4];
#pragma unroll
    for (int nt = 0; nt < 8; nt++)
#pragma unroll
        for (int j = 0; j < 4; j++) acc[nt][j] = 0.f;

    uint32_t aBase = smem_u32(As) +
        (uint32_t)(((mt + (lane & 15)) * 72 + (lane >> 4) * 8) * 2);
    uint32_t bBase = smem_u32(Bs) +
        (uint32_t)(((ng + (lane & 7) + ((lane >> 4) << 3)) * 72 + ((lane >> 3) & 1) * 8) * 2);

#pragma unroll 1
    for (int kc = 0; kc < 8; kc++) {
#pragma unroll
        for (int i = 0; i < 2; i++) {
            int t = i * 256 + tid;
            int r = t >> 3, c0 = (t & 7) * 8;
            *(uint4*)(As + r * 72 + c0) =
                *(const uint4*)(g_h1 + (size_t)(m0 + r) * 512 + kc * 64 + c0);
        }
#pragma unroll
        for (int i = 0; i < 4; i++) {
            int t = i * 256 + tid;
            int r = t >> 3, c0 = (t & 7) * 8;
            *(uint4*)(Bs + r * 72 + c0) =
                *(const uint4*)(wT + (size_t)(n0 + r) * 512 + kc * 64 + c0);
        }
        __syncthreads();
#pragma unroll
        for (int ks = 0; ks < 4; ks++) {
            uint32_t a[4];
            LDSM4(a, aBase + ks * 32);
#pragma unroll
            for (int ntp = 0; ntp < 4; ntp++) {
                uint32_t b[4];
                LDSM4(b, bBase + ntp * (16 * 72 * 2) + ks * 32);
                mma16816(acc[2 * ntp],     a, b + 0);
                mma16816(acc[2 * ntp + 1], a, b + 2);
            }
        }
        __syncthreads();
    }

    int gid = lane >> 2, tig = lane & 3;
    int row = m0 + mt + gid;
#pragma unroll
    for (int nt = 0; nt < 8; nt++) {
        int col = n0 + ng + nt * 8 + 2 * tig;
        float b0 = bias[col], b1 = bias[col + 1];
        g_h2[(size_t)row * 256 + col]           = lrelu(acc[nt][0] + b0);
        g_h2[(size_t)row * 256 + col + 1]       = lrelu(acc[nt][1] + b1);
        g_h2[(size_t)(row + 8) * 256 + col]     = lrelu(acc[nt][2] + b0);
        g_h2[(size_t)(row + 8) * 256 + col + 1] = lrelu(acc[nt][3] + b1);
    }
}

// ---------------- head3: 256 -> 12 (fp32, no lrelu) ----------------
__global__ __launch_bounds__(192) void head3_kernel(const float* __restrict__ wf3,
                                                    const float* __restrict__ bf3,
                                                    float* __restrict__ out) {
    int blk = blockIdx.x, tid = threadIdx.x;
    int r = tid / 12, c = tid - r * 12;
    int row = blk * 16 + r;
    const float* h = g_h2 + (size_t)row * 256;
    float a0 = bf3[c], a1 = 0.f, a2 = 0.f, a3 = 0.f;
#pragma unroll 4
    for (int cm = 0; cm < 256; cm += 4) {
        a0 = fmaf(h[cm + 0], wf3[(cm + 0) * 12 + c], a0);
        a1 = fmaf(h[cm + 1], wf3[(cm + 1) * 12 + c], a1);
        a2 = fmaf(h[cm + 2], wf3[(cm + 2) * 12 + c], a2);
        a3 = fmaf(h[cm + 3], wf3[(cm + 3) * 12 + c], a3);
    }
    out[(size_t)row * 12 + c] = (a0 + a1) + (a2 + a3);
}

// ---------------- launch ----------------
constexpr int SMEM_P1 = (2 * 64 * 4 + 32 * 4 + 64) * 4;            //   2816
constexpr int SMEM_P2 = (2 * 64 * 68 + 32 * 68 + 64) * 4;          //  43776
constexpr int SMEM_P3 = (2 * 128 * 132 + 32 * 132 + 128) * 4;      // 152576
constexpr int SMEM_E12 = (256 * 72 + 64 * 72) * 2 + 256 * 4;       //  47104
constexpr int SMEM_E3  = (256 * 136 + 64 * 136) * 2 + 256 * 4;     //  88064

extern "C" void kernel_launch(void* const* d_in, const int* in_sizes, int n_in,
                              void* d_out, int out_size) {
    const float* x   = (const float*)d_in[0];
    const float* pos = (const float*)d_in[1];
    const float* w1a = (const float*)d_in[2];
    const float* b1a = (const float*)d_in[3];
    const float* w1b = (const float*)d_in[4];
    const float* b1b = (const float*)d_in[5];
    const float* w2a = (const float*)d_in[6];
    const float* b2a = (const float*)d_in[7];
    const float* w2b = (const float*)d_in[8];
    const float* b2b = (const float*)d_in[9];
    const float* w3a = (const float*)d_in[10];
    const float* b3a = (const float*)d_in[11];
    const float* w3b = (const float*)d_in[12];
    const float* b3b = (const float*)d_in[13];
    const float* wf1 = (const float*)d_in[14];
    const float* bf1 = (const float*)d_in[15];
    const float* wf2 = (const float*)d_in[16];
    const float* bf2 = (const float*)d_in[17];
    const float* wf3 = (const float*)d_in[18];
    const float* bf3 = (const float*)d_in[19];
    float* out = (float*)d_out;

    float *x1p, *x2p, *x3p;
    __half *wt1p, *wt2p, *wt3p, *wf1Tp, *wf2Tp;
    cudaGetSymbolAddress((void**)&x1p, g_x1);
    cudaGetSymbolAddress((void**)&x2p, g_x2);
    cudaGetSymbolAddress((void**)&x3p, g_x3);
    cudaGetSymbolAddress((void**)&wt1p, g_wbT1);
    cudaGetSymbolAddress((void**)&wt2p, g_wbT2);
    cudaGetSymbolAddress((void**)&wt3p, g_wbT3);
    cudaGetSymbolAddress((void**)&wf1Tp, g_wf1T);
    cudaGetSymbolAddress((void**)&wf2Tp, g_wf2T);

    static bool attr_done = false;
    if (!attr_done) {
        cudaFuncSetAttribute(proj_kernel<128, 128, 132>,
                             cudaFuncAttributeMaxDynamicSharedMemorySize, SMEM_P3);
        cudaFuncSetAttribute(edge_mma<64, 64, 1>,
                             cudaFuncAttributeMaxDynamicSharedMemorySize, SMEM_E12);
        cudaFuncSetAttribute(edge_mma<64, 128, 2>,
                             cudaFuncAttributeMaxDynamicSharedMemorySize, SMEM_E12);
        cudaFuncSetAttribute(edge_mma<128, 512, 8>,
                             cudaFuncAttributeMaxDynamicSharedMemorySize, SMEM_E3);
        attr_done = true;
    }

    // slot 4 is the launch ncu captures -> knn this round
    proj_kernel<3, 64, 4><<<BN_ / 32, 256, SMEM_P1>>>(x, w1a, b1a);        // 1
    prep_wb<<<304, 256>>>(w1b, w2b, w3b, wt1p, wt2p, wt3p);                // 2
    prep_wf<<<1920, 256>>>(wf1, wf2, wf1Tp, wf2Tp);                        // 3
    knn_kernel<<<BN_, 256>>>(pos);                                         // 4 <- ncu

    // block1: 3 -> 64 -> 64
    edge_mma<64, 64, 1><<<BN_ / 8, 256, SMEM_E12>>>(wt1p, b1b, x1p);
    // block2: 64 -> 64 -> 128
    proj_kernel<64, 64, 68><<<BN_ / 32, 256, SMEM_P2>>>(x1p, w2a, b2a);
    edge_mma<64, 128, 2><<<BN_ / 8, 256, SMEM_E12>>>(wt2p, b2b, x2p);
    // block3: 128 -> 128 -> 512
    proj_kernel<128, 128, 132><<<BN_ / 32, 256, SMEM_P3>>>(x2p, w3a, b3a);
    edge_mma<128, 512, 8><<<BN_ / 8, 256, SMEM_E3>>>(wt3p, b3b, x3p);

    // head: 704 -> 512 (f16 mma) -> 256 (f16 mma) -> 12 (fp32)
    head1_mma<<<dim3(BN_ / 64, 4), 256>>>(wf1Tp, bf1);
    head2_mma<<<dim3(BN_ / 64, 2), 256>>>(wf2Tp, bf2);
    head3_kernel<<<BN_ / 16, 192>>>(wf3, bf3, out);
}

// round 10
// speedup vs baseline: 3.0360x; 1.2884x over previous
#include <cuda_runtime.h>
#include <cuda_fp16.h>
#include <cstdint>

// DGCNN: B=8, N=2048, k=32.  (sm_103 PTX target -> mma.sync f16 + ldmatrix)
// proj1 -> prep_wb -> prep_wf -> knn -> edge1/2/3 (f16 mma) -> head1/2 (f16 mma) -> head3.
// Edge trick: feat@wa = p[point] + q[neighbor]; per-edge work is
// lrelu(p+q) then CMID x COUT GEMM + max over k (lrelu monotone -> max last).
// R10: knn selection rebuilt on redux.sync.min.u32 (2 REDUX/iter instead of
// 10 shfl.b32 + u64 compare chains). Same selection semantics, ~3x less ALU.

#define NEG 0.2f
constexpr int B_  = 8;
constexpr int N_  = 2048;
constexpr int BN_ = B_ * N_;   // 16384
constexpr int K_  = 32;

// ---- scratch (device globals; no runtime allocation allowed) ----
__device__ int    g_idx[BN_ * K_];
__device__ float  g_p[BN_ * 128];
__device__ float  g_q[BN_ * 128];
__device__ float  g_x1[BN_ * 64];
__device__ float  g_x2[BN_ * 128];
__device__ float  g_x3[BN_ * 512];
__device__ __half g_h1[BN_ * 512];
__device__ float  g_h2[BN_ * 256];
__device__ __half g_wbT1[64 * 64];     // w1b^T [64][64]
__device__ __half g_wbT2[128 * 64];    // w2b^T [128][64]
__device__ __half g_wbT3[512 * 128];   // w3b^T [512][128]
__device__ __half g_wf1T[512 * 704];   // wf1^T [512][704]
__device__ __half g_wf2T[256 * 512];   // wf2^T [256][512]

__device__ __forceinline__ float lrelu(float v) { return v >= 0.f ? v : NEG * v; }

__device__ __forceinline__ uint32_t pack_f16x2(float lo, float hi) {
    uint32_t u;
    asm("cvt.rn.f16x2.f32 %0, %1, %2;" : "=r"(u) : "f"(hi), "f"(lo));
    return u;
}

__device__ __forceinline__ uint32_t smem_u32(const void* p) {
    uint32_t a;
    asm("{ .reg .u64 t; cvta.to.shared.u64 t, %1; cvt.u32.u64 %0, t; }" : "=r"(a) : "l"(p));
    return a;
}

__device__ __forceinline__ void mma16816(float d[4], const uint32_t a[4],
                                         const uint32_t b[2]) {
    asm volatile(
        "mma.sync.aligned.m16n8k16.row.col.f32.f16.f16.f32 "
        "{%0,%1,%2,%3}, {%4,%5,%6,%7}, {%8,%9}, {%0,%1,%2,%3};\n"
        : "+f"(d[0]), "+f"(d[1]), "+f"(d[2]), "+f"(d[3])
        : "r"(a[0]), "r"(a[1]), "r"(a[2]), "r"(a[3]), "r"(b[0]), "r"(b[1]));
}

#define LDSM4(r, addr) \
    asm volatile("ldmatrix.sync.aligned.m8n8.x4.shared.b16 {%0,%1,%2,%3}, [%4];" \
                 : "=r"((r)[0]), "=r"((r)[1]), "=r"((r)[2]), "=r"((r)[3]) \
                 : "r"(addr))

// ---------------- edge-weight transpose + f16 (4096 + 8192 + 65536 = 77824) ---
__global__ void prep_wb(const float* __restrict__ w1, const float* __restrict__ w2,
                        const float* __restrict__ w3, __half* __restrict__ t1,
                        __half* __restrict__ t2, __half* __restrict__ t3) {
    int t = blockIdx.x * 256 + threadIdx.x;
    if (t < 4096) {
        int k = t >> 6, n = t & 63;
        t1[n * 64 + k] = __float2half_rn(w1[t]);
    } else if (t < 12288) {
        int e = t - 4096;
        int k = e >> 7, n = e & 127;
        t2[n * 64 + k] = __float2half_rn(w2[e]);
    } else if (t < 77824) {
        int e = t - 12288;
        int k = e >> 9, n = e & 511;
        t3[n * 128 + k] = __float2half_rn(w3[e]);
    }
}

// ---------------- head-weight transpose + f16 (360448 + 131072 = 491520) ------
__global__ void prep_wf(const float* __restrict__ wf1, const float* __restrict__ wf2,
                        __half* __restrict__ t1, __half* __restrict__ t2) {
    int t = blockIdx.x * 256 + threadIdx.x;
    if (t < 360448) {            // out-indexed: n = t/704, k = t%704
        int n = t / 704, k = t - n * 704;
        t1[t] = __float2half_rn(wf1[k * 512 + n]);
    } else {
        int e = t - 360448;
        int n = e >> 9, k = e & 511;
        t2[e] = __float2half_rn(wf2[k * 256 + n]);
    }
}

// ---------------- kNN: REDUX-based top-32 selection ----------------
// Key order: ordered-u32(d2) asc, tie -> lowest index (= jax.lax.top_k(-d2)).
// Phase 1: each warp owns 256 candidates (8 slots/lane, idx implicit in
// (slot,lane)); 32 rounds of [REDUX min val; REDUX min (slot<<5|lane) among
// matching lanes; winning lane invalidates + rescans (unrolled u32 scan)].
// Phase 2: warp 0 merges the 8x32 (val,idx) u64 candidates with the same
// hi/lo REDUX split.
__global__ __launch_bounds__(256) void knn_kernel(const float* __restrict__ pos) {
    __shared__ unsigned long long cand[256];
    int point = blockIdx.x;
    int base  = (point >> 11) * N_;
    int tid   = threadIdx.x;
    int w     = tid >> 5, lane = tid & 31;

    float px = pos[point * 3 + 0], py = pos[point * 3 + 1], pz = pos[point * 3 + 2];
    float sqn = fmaf(pz, pz, fmaf(py, py, px * px));

    unsigned vals[8];
#pragma unroll
    for (int i = 0; i < 8; i++) {
        int m = (w << 8) + (i << 5) + lane;
        const float* pm = pos + (size_t)(base + m) * 3;
        float mx = pm[0], my = pm[1], mz = pm[2];
        float dot = fmaf(pz, mz, fmaf(py, my, px * mx));
        float sqm = fmaf(mz, mz, fmaf(my, my, mx * mx));
        float d2  = (sqn - 2.f * dot) + sqm;
        unsigned u = __float_as_uint(d2);
        vals[i] = (u & 0x80000000u) ? ~u : (u | 0x80000000u);
    }
    // local argmin (earliest slot on ties -> lowest idx within lane)
    unsigned lval = vals[0];
    int      lslot = 0;
#pragma unroll
    for (int i = 1; i < 8; i++)
        if (vals[i] < lval) { lval = vals[i]; lslot = i; }

#pragma unroll 1
    for (int it = 0; it < K_; it++) {
        unsigned m    = __reduce_min_sync(0xffffffffu, lval);
        unsigned prop = (lval == m) ? (unsigned)((lslot << 5) | lane) : 0xFFFFFFFFu;
        unsigned widx = __reduce_min_sync(0xffffffffu, prop);
        if (lane == 0)
            cand[(w << 5) + it] =
                ((unsigned long long)m << 32) | (unsigned)((w << 8) + widx);
        if (prop == widx) {          // unique winner: invalidate + rescan
            unsigned bv = 0xFFFFFFFFu;
            int bs = 0;
#pragma unroll
            for (int i = 0; i < 8; i++) {
                if (i == lslot) vals[i] = 0xFFFFFFFFu;
                if (vals[i] < bv) { bv = vals[i]; bs = i; }
            }
            lval = bv; lslot = bs;
        }
    }
    __syncthreads();

    if (w == 0) {
        unsigned long long c[8];
#pragma unroll
        for (int i = 0; i < 8; i++) c[i] = cand[(i << 5) + lane];
        unsigned long long lk = c[0];
        int ls = 0;
#pragma unroll
        for (int i = 1; i < 8; i++)
            if (c[i] < lk) { lk = c[i]; ls = i; }

#pragma unroll 1
        for (int it = 0; it < K_; it++) {
            unsigned mhi  = __reduce_min_sync(0xffffffffu, (unsigned)(lk >> 32));
            unsigned prop = ((unsigned)(lk >> 32) == mhi) ? (unsigned)lk : 0xFFFFFFFFu;
            unsigned mlo  = __reduce_min_sync(0xffffffffu, prop);
            if (lane == 0) g_idx[point * K_ + it] = base + (int)mlo;
            if (prop == mlo) {       // unique winner (idx unique)
                unsigned long long bk = ~0ull;
                int bs = 0;
#pragma unroll
                for (int i = 0; i < 8; i++) {
                    if (i == ls) c[i] = ~0ull;
                    if (c[i] < bk) { bk = c[i]; bs = i; }
                }
                lk = bk; ls = bs;
            }
        }
    }
}

// ---------------- batched per-point projections p,q ----------------
// 32 points per block; weights staged in smem once.
template <int CIN, int CMID, int CINP>
__global__ __launch_bounds__(256) void proj_kernel(const float* __restrict__ x,
                                                   const float* __restrict__ wa,
                                                   const float* __restrict__ ba) {
    extern __shared__ __align__(16) float smf[];
    float* wts = smf;                      // [CMID][CINP]
    float* wqs = wts + CMID * CINP;        // [CMID][CINP]
    float* xs  = wqs + CMID * CINP;        // [32][CINP]
    float* bas = xs + 32 * CINP;           // [CMID]
    int tid = threadIdx.x;
    int p0  = blockIdx.x * 32;

    for (int t = tid; t < CIN * CMID; t += 256) {
        int ci = t / CMID, cm = t - ci * CMID;
        float top = wa[t], bot = wa[CIN * CMID + t];
        wts[cm * CINP + ci] = top - bot;
        wqs[cm * CINP + ci] = bot;
    }
    for (int t = tid; t < 32 * CIN; t += 256) {
        int pp = t / CIN, ci = t - pp * CIN;
        xs[pp * CINP + ci] = x[(size_t)(p0 + pp) * CIN + ci];
    }
    if (tid < CMID) bas[tid] = ba[tid];
    __syncthreads();

    constexpr int LANES = 256 / CMID;
    int li = tid / CMID, cm = tid - li * CMID;
    const float* wtr = wts + cm * CINP;
    const float* wqr = wqs + cm * CINP;
    float bias = bas[cm];

    for (int pp = li; pp < 32; pp += LANES) {
        const float* xr = xs + pp * CINP;
        float pa = bias, qa = 0.f;
        if constexpr (CIN % 4 == 0) {
#pragma unroll
            for (int ci = 0; ci < CIN; ci += 4) {
                float4 xv = *(const float4*)(xr + ci);
                float4 wt4 = *(const float4*)(wtr + ci);
                float4 wq4 = *(const float4*)(wqr + ci);
                pa = fmaf(xv.x, wt4.x, pa); qa = fmaf(xv.x, wq4.x, qa);
                pa = fmaf(xv.y, wt4.y, pa); qa = fmaf(xv.y, wq4.y, qa);
                pa = fmaf(xv.z, wt4.z, pa); qa = fmaf(xv.z, wq4.z, qa);
                pa = fmaf(xv.w, wt4.w, pa); qa = fmaf(xv.w, wq4.w, qa);
            }
        } else {
#pragma unroll
            for (int ci = 0; ci < CIN; ci++) {
                float xv = xr[ci];
                pa = fmaf(xv, wtr[ci], pa);
                qa = fmaf(xv, wqr[ci], qa);
            }
        }
        g_p[(size_t)(p0 + pp) * CMID + cm] = pa;
        g_q[(size_t)(p0 + pp) * CMID + cm] = qa;
    }
}

// ---------------- edge blocks: f16 mma + ldmatrix, 256 thr, 2 blocks/SM -------
// Block: 8 points (A = 256 edge rows loaded ONCE), loops NITER n-slices of 64.
template <int CMID, int COUT, int NITER>
__global__ __launch_bounds__(256, 2) void edge_mma(const __half* __restrict__ wbT,
                                                   const float* __restrict__ bb,
                                                   float* __restrict__ out) {
    constexpr int PT    = 8;
    constexpr int NT    = 64;
    constexpr int KP    = CMID + 8;
    constexpr int AROWS = PT * 32;         // 256
    constexpr int CPR8  = CMID / 8;
    extern __shared__ __align__(16) char smraw[];
    __half* As = (__half*)smraw;                    // [256][KP]
    __half* Bs = As + AROWS * KP;                   // [64][KP]
    int*  nidx = (int*)(Bs + NT * KP);              // [256]

    int tid = threadIdx.x, w = tid >> 5, lane = tid & 31;
    int p0 = blockIdx.x * PT;

    nidx[tid] = g_idx[p0 * K_ + tid];
    __syncthreads();

#pragma unroll
    for (int i = 0; i < AROWS * CPR8 / 256; i++) {
        int e  = i * 256 + tid;
        int r  = e / CPR8;
        int c0 = (e - r * CPR8) * 8;
        const float* qr = g_q + (size_t)nidx[r] * CMID + c0;
        const float* pr = g_p + (size_t)(p0 + (r >> 5)) * CMID + c0;
        float4 qa = *(const float4*)qr, qb = *(const float4*)(qr + 4);
        float4 pa = *(const float4*)pr, pb = *(const float4*)(pr + 4);
        uint4 pk = { pack_f16x2(lrelu(pa.x + qa.x), lrelu(pa.y + qa.y)),
                     pack_f16x2(lrelu(pa.z + qa.z), lrelu(pa.w + qa.w)),
                     pack_f16x2(lrelu(pb.x + qb.x), lrelu(pb.y + qb.y)),
                     pack_f16x2(lrelu(pb.z + qb.z), lrelu(pb.w + qb.w)) };
        *(uint4*)(As + r * KP + c0) = pk;
    }

    uint32_t aBase = smem_u32(As) +
        (uint32_t)(((w * 32 + (lane & 15)) * KP + (lane >> 4) * 8) * 2);
    uint32_t bBase = smem_u32(Bs) +
        (uint32_t)((((lane & 7) + ((lane >> 4) << 3)) * KP + ((lane >> 3) & 1) * 8) * 2);
    int pglob = p0 + w;

#pragma unroll 1
    for (int it = 0; it < NITER; it++) {
        int n0 = it * NT;
        __syncthreads();
#pragma unroll
        for (int i = 0; i < NT * CPR8 / 256; i++) {
            int e  = i * 256 + tid;
            int r  = e / CPR8;
            int c0 = (e - r * CPR8) * 8;
            *(uint4*)(Bs + r * KP + c0) =
                *(const uint4*)(wbT + (size_t)(n0 + r) * CMID + c0);
        }
        __syncthreads();

        float acc[2][8][4];
#pragma unroll
        for (int mt = 0; mt < 2; mt++)
#pragma unroll
            for (int nt = 0; nt < 8; nt++)
#pragma unroll
                for (int j = 0; j < 4; j++) acc[mt][nt][j] = 0.f;

#pragma unroll 1
        for (int ks = 0; ks < CMID / 16; ks++) {
            uint32_t a0[4], a1[4];
            LDSM4(a0, aBase + ks * 32);
            LDSM4(a1, aBase + 16 * KP * 2 + ks * 32);
#pragma unroll
            for (int ntp = 0; ntp < 4; ntp++) {
                uint32_t b[4];
                LDSM4(b, bBase + ntp * (16 * KP * 2) + ks * 32);
                mma16816(acc[0][2 * ntp],     a0, b + 0);
                mma16816(acc[1][2 * ntp],     a1, b + 0);
                mma16816(acc[0][2 * ntp + 1], a0, b + 2);
                mma16816(acc[1][2 * ntp + 1], a1, b + 2);
            }
        }

#pragma unroll
        for (int nt = 0; nt < 8; nt++) {
            float v0 = fmaxf(fmaxf(acc[0][nt][0], acc[0][nt][2]),
                             fmaxf(acc[1][nt][0], acc[1][nt][2]));
            float v1 = fmaxf(fmaxf(acc[0][nt][1], acc[0][nt][3]),
                             fmaxf(acc[1][nt][1], acc[1][nt][3]));
#pragma unroll
            for (int s = 4; s < 32; s <<= 1) {
                v0 = fmaxf(v0, __shfl_xor_sync(0xffffffffu, v0, s));
                v1 = fmaxf(v1, __shfl_xor_sync(0xffffffffu, v1, s));
            }
            if (lane < 4) {
                int col = n0 + nt * 8 + 2 * lane;
                out[(size_t)pglob * COUT + col]     = lrelu(v0 + bb[col]);
                out[(size_t)pglob * COUT + col + 1] = lrelu(v1 + bb[col + 1]);
            }
        }
    }
}

// ---------------- head1: concat(704) -> 512 via f16 mma, lrelu, h1 f16 --------
__global__ __launch_bounds__(256, 2) void head1_mma(const __half* __restrict__ wT,
                                                    const float* __restrict__ bias) {
    __shared__ __align__(16) __half As[64 * 72];
    __shared__ __align__(16) __half Bs[128 * 72];
    int tid = threadIdx.x, w = tid >> 5, lane = tid & 31;
    int m0 = blockIdx.x * 64, n0 = blockIdx.y * 128;
    int mt = (w >> 1) * 16, ng = (w & 1) * 64;

    float acc[8][4];
#pragma unroll
    for (int nt = 0; nt < 8; nt++)
#pragma unroll
        for (int j = 0; j < 4; j++) acc[nt][j] = 0.f;

    uint32_t aBase = smem_u32(As) +
        (uint32_t)(((mt + (lane & 15)) * 72 + (lane >> 4) * 8) * 2);
    uint32_t bBase = smem_u32(Bs) +
        (uint32_t)(((ng + (lane & 7) + ((lane >> 4) << 3)) * 72 + ((lane >> 3) & 1) * 8) * 2);

#pragma unroll 1
    for (int kc = 0; kc < 11; kc++) {
        const float* src; int stride, off;
        if (kc == 0)      { src = g_x1; stride = 64;  off = 0; }
        else if (kc <= 2) { src = g_x2; stride = 128; off = (kc - 1) * 64; }
        else              { src = g_x3; stride = 512; off = (kc - 3) * 64; }
#pragma unroll
        for (int i = 0; i < 2; i++) {
            int t = i * 256 + tid;
            int r = t >> 3, c0 = (t & 7) * 8;
            const float* sp = src + (size_t)(m0 + r) * stride + off + c0;
            float4 a = *(const float4*)sp, b = *(const float4*)(sp + 4);
            uint4 pk = { pack_f16x2(a.x, a.y), pack_f16x2(a.z, a.w),
                         pack_f16x2(b.x, b.y), pack_f16x2(b.z, b.w) };
            *(uint4*)(As + r * 72 + c0) = pk;
        }
#pragma unroll
        for (int i = 0; i < 4; i++) {
            int t = i * 256 + tid;
            int r = t >> 3, c0 = (t & 7) * 8;
            *(uint4*)(Bs + r * 72 + c0) =
                *(const uint4*)(wT + (size_t)(n0 + r) * 704 + kc * 64 + c0);
        }
        __syncthreads();
#pragma unroll
        for (int ks = 0; ks < 4; ks++) {
            uint32_t a[4];
            LDSM4(a, aBase + ks * 32);
#pragma unroll
            for (int ntp = 0; ntp < 4; ntp++) {
                uint32_t b[4];
                LDSM4(b, bBase + ntp * (16 * 72 * 2) + ks * 32);
                mma16816(acc[2 * ntp],     a, b + 0);
                mma16816(acc[2 * ntp + 1], a, b + 2);
            }
        }
        __syncthreads();
    }

    int gid = lane >> 2, tig = lane & 3;
    int row = m0 + mt + gid;
#pragma unroll
    for (int nt = 0; nt < 8; nt++) {
        int col = n0 + ng + nt * 8 + 2 * tig;
        float b0 = bias[col], b1 = bias[col + 1];
        *(uint32_t*)(g_h1 + (size_t)row * 512 + col) =
            pack_f16x2(lrelu(acc[nt][0] + b0), lrelu(acc[nt][1] + b1));
        *(uint32_t*)(g_h1 + (size_t)(row + 8) * 512 + col) =
            pack_f16x2(lrelu(acc[nt][2] + b0), lrelu(acc[nt][3] + b1));
    }
}

// ---------------- head2: 512 -> 256 via f16 mma, lrelu, h2 fp32 ---------------
__global__ __launch_bounds__(256, 2) void head2_mma(const __half* __restrict__ wT,
                                                    const float* __restrict__ bias) {
    __shared__ __align__(16) __half As[64 * 72];
    __shared__ __align__(16) __half Bs[128 * 72];
    int tid = threadIdx.x, w = tid >> 5, lane = tid & 31;
    int m0 = blockIdx.x * 64, n0 = blockIdx.y * 128;
    int mt = (w >> 1) * 16, ng = (w & 1) * 64;

    float acc[8][4];
#pragma unroll
    for (int nt = 0; nt < 8; nt++)
#pragma unroll
        for (int j = 0; j < 4; j++) acc[nt][j] = 0.f;

    uint32_t aBase = smem_u32(As) +
        (uint32_t)(((mt + (lane & 15)) * 72 + (lane >> 4) * 8) * 2);
    uint32_t bBase = smem_u32(Bs) +
        (uint32_t)(((ng + (lane & 7) + ((lane >> 4) << 3)) * 72 + ((lane >> 3) & 1) * 8) * 2);

#pragma unroll 1
    for (int kc = 0; kc < 8; kc++) {
#pragma unroll
        for (int i = 0; i < 2; i++) {
            int t = i * 256 + tid;
            int r = t >> 3, c0 = (t & 7) * 8;
            *(uint4*)(As + r * 72 + c0) =
                *(const uint4*)(g_h1 + (size_t)(m0 + r) * 512 + kc * 64 + c0);
        }
#pragma unroll
        for (int i = 0; i < 4; i++) {
            int t = i * 256 + tid;
            int r = t >> 3, c0 = (t & 7) * 8;
            *(uint4*)(Bs + r * 72 + c0) =
                *(const uint4*)(wT + (size_t)(n0 + r) * 512 + kc * 64 + c0);
        }
        __syncthreads();
#pragma unroll
        for (int ks = 0; ks < 4; ks++) {
            uint32_t a[4];
            LDSM4(a, aBase + ks * 32);
#pragma unroll
            for (int ntp = 0; ntp < 4; ntp++) {
                uint32_t b[4];
                LDSM4(b, bBase + ntp * (16 * 72 * 2) + ks * 32);
                mma16816(acc[2 * ntp],     a, b + 0);
                mma16816(acc[2 * ntp + 1], a, b + 2);
            }
        }
        __syncthreads();
    }

    int gid = lane >> 2, tig = lane & 3;
    int row = m0 + mt + gid;
#pragma unroll
    for (int nt = 0; nt < 8; nt++) {
        int col = n0 + ng + nt * 8 + 2 * tig;
        float b0 = bias[col], b1 = bias[col + 1];
        g_h2[(size_t)row * 256 + col]           = lrelu(acc[nt][0] + b0);
        g_h2[(size_t)row * 256 + col + 1]       = lrelu(acc[nt][1] + b1);
        g_h2[(size_t)(row + 8) * 256 + col]     = lrelu(acc[nt][2] + b0);
        g_h2[(size_t)(row + 8) * 256 + col + 1] = lrelu(acc[nt][3] + b1);
    }
}

// ---------------- head3: 256 -> 12 (fp32, no lrelu) ----------------
__global__ __launch_bounds__(192) void head3_kernel(const float* __restrict__ wf3,
                                                    const float* __restrict__ bf3,
                                                    float* __restrict__ out) {
    int blk = blockIdx.x, tid = threadIdx.x;
    int r = tid / 12, c = tid - r * 12;
    int row = blk * 16 + r;
    const float* h = g_h2 + (size_t)row * 256;
    float a0 = bf3[c], a1 = 0.f, a2 = 0.f, a3 = 0.f;
#pragma unroll 4
    for (int cm = 0; cm < 256; cm += 4) {
        a0 = fmaf(h[cm + 0], wf3[(cm + 0) * 12 + c], a0);
        a1 = fmaf(h[cm + 1], wf3[(cm + 1) * 12 + c], a1);
        a2 = fmaf(h[cm + 2], wf3[(cm + 2) * 12 + c], a2);
        a3 = fmaf(h[cm + 3], wf3[(cm + 3) * 12 + c], a3);
    }
    out[(size_t)row * 12 + c] = (a0 + a1) + (a2 + a3);
}

// ---------------- launch ----------------
constexpr int SMEM_P1 = (2 * 64 * 4 + 32 * 4 + 64) * 4;            //   2816
constexpr int SMEM_P2 = (2 * 64 * 68 + 32 * 68 + 64) * 4;          //  43776
constexpr int SMEM_P3 = (2 * 128 * 132 + 32 * 132 + 128) * 4;      // 152576
constexpr int SMEM_E12 = (256 * 72 + 64 * 72) * 2 + 256 * 4;       //  47104
constexpr int SMEM_E3  = (256 * 136 + 64 * 136) * 2 + 256 * 4;     //  88064

extern "C" void kernel_launch(void* const* d_in, const int* in_sizes, int n_in,
                              void* d_out, int out_size) {
    const float* x   = (const float*)d_in[0];
    const float* pos = (const float*)d_in[1];
    const float* w1a = (const float*)d_in[2];
    const float* b1a = (const float*)d_in[3];
    const float* w1b = (const float*)d_in[4];
    const float* b1b = (const float*)d_in[5];
    const float* w2a = (const float*)d_in[6];
    const float* b2a = (const float*)d_in[7];
    const float* w2b = (const float*)d_in[8];
    const float* b2b = (const float*)d_in[9];
    const float* w3a = (const float*)d_in[10];
    const float* b3a = (const float*)d_in[11];
    const float* w3b = (const float*)d_in[12];
    const float* b3b = (const float*)d_in[13];
    const float* wf1 = (const float*)d_in[14];
    const float* bf1 = (const float*)d_in[15];
    const float* wf2 = (const float*)d_in[16];
    const float* bf2 = (const float*)d_in[17];
    const float* wf3 = (const float*)d_in[18];
    const float* bf3 = (const float*)d_in[19];
    float* out = (float*)d_out;

    float *x1p, *x2p, *x3p;
    __half *wt1p, *wt2p, *wt3p, *wf1Tp, *wf2Tp;
    cudaGetSymbolAddress((void**)&x1p, g_x1);
    cudaGetSymbolAddress((void**)&x2p, g_x2);
    cudaGetSymbolAddress((void**)&x3p, g_x3);
    cudaGetSymbolAddress((void**)&wt1p, g_wbT1);
    cudaGetSymbolAddress((void**)&wt2p, g_wbT2);
    cudaGetSymbolAddress((void**)&wt3p, g_wbT3);
    cudaGetSymbolAddress((void**)&wf1Tp, g_wf1T);
    cudaGetSymbolAddress((void**)&wf2Tp, g_wf2T);

    static bool attr_done = false;
    if (!attr_done) {
        cudaFuncSetAttribute(proj_kernel<128, 128, 132>,
                             cudaFuncAttributeMaxDynamicSharedMemorySize, SMEM_P3);
        cudaFuncSetAttribute(edge_mma<64, 64, 1>,
                             cudaFuncAttributeMaxDynamicSharedMemorySize, SMEM_E12);
        cudaFuncSetAttribute(edge_mma<64, 128, 2>,
                             cudaFuncAttributeMaxDynamicSharedMemorySize, SMEM_E12);
        cudaFuncSetAttribute(edge_mma<128, 512, 8>,
                             cudaFuncAttributeMaxDynamicSharedMemorySize, SMEM_E3);
        attr_done = true;
    }

    // slot 4 is the launch ncu captures -> knn stays there to verify the fix
    proj_kernel<3, 64, 4><<<BN_ / 32, 256, SMEM_P1>>>(x, w1a, b1a);        // 1
    prep_wb<<<304, 256>>>(w1b, w2b, w3b, wt1p, wt2p, wt3p);                // 2
    prep_wf<<<1920, 256>>>(wf1, wf2, wf1Tp, wf2Tp);                        // 3
    knn_kernel<<<BN_, 256>>>(pos);                                         // 4 <- ncu

    // block1: 3 -> 64 -> 64
    edge_mma<64, 64, 1><<<BN_ / 8, 256, SMEM_E12>>>(wt1p, b1b, x1p);
    // block2: 64 -> 64 -> 128
    proj_kernel<64, 64, 68><<<BN_ / 32, 256, SMEM_P2>>>(x1p, w2a, b2a);
    edge_mma<64, 128, 2><<<BN_ / 8, 256, SMEM_E12>>>(wt2p, b2b, x2p);
    // block3: 128 -> 128 -> 512
    proj_kernel<128, 128, 132><<<BN_ / 32, 256, SMEM_P3>>>(x2p, w3a, b3a);
    edge_mma<128, 512, 8><<<BN_ / 8, 256, SMEM_E3>>>(wt3p, b3b, x3p);

    // head: 704 -> 512 (f16 mma) -> 256 (f16 mma) -> 12 (fp32)
    head1_mma<<<dim3(BN_ / 64, 4), 256>>>(wf1Tp, bf1);
    head2_mma<<<dim3(BN_ / 64, 2), 256>>>(wf2Tp, bf2);
    head3_kernel<<<BN_ / 16, 192>>>(wf3, bf3, out);
}

// round 11
// speedup vs baseline: 3.9660x; 1.3063x over previous
#include <cuda_runtime.h>
#include <cuda_fp16.h>
#include <cstdint>

// DGCNN: B=8, N=2048, k=32.  (sm_103 PTX target -> mma.sync f16 + ldmatrix)
// proj1 -> prep_wb -> prep_wf -> knn -> edge1/2/3 (f16 mma) -> head1/2 (f16 mma) -> head3.
// R11: knn selection with per-lane pre-sorted keys (19-CE network) + O(7)-shift
// pop, replacing the 40-op divergent rescan per round. Same selection sets.

#define NEG 0.2f
constexpr int B_  = 8;
constexpr int N_  = 2048;
constexpr int BN_ = B_ * N_;   // 16384
constexpr int K_  = 32;

// ---- scratch (device globals; no runtime allocation allowed) ----
__device__ int    g_idx[BN_ * K_];
__device__ float  g_p[BN_ * 128];
__device__ float  g_q[BN_ * 128];
__device__ float  g_x1[BN_ * 64];
__device__ float  g_x2[BN_ * 128];
__device__ float  g_x3[BN_ * 512];
__device__ __half g_h1[BN_ * 512];
__device__ float  g_h2[BN_ * 256];
__device__ __half g_wbT1[64 * 64];
__device__ __half g_wbT2[128 * 64];
__device__ __half g_wbT3[512 * 128];
__device__ __half g_wf1T[512 * 704];
__device__ __half g_wf2T[256 * 512];

__device__ __forceinline__ float lrelu(float v) { return v >= 0.f ? v : NEG * v; }

__device__ __forceinline__ uint32_t pack_f16x2(float lo, float hi) {
    uint32_t u;
    asm("cvt.rn.f16x2.f32 %0, %1, %2;" : "=r"(u) : "f"(hi), "f"(lo));
    return u;
}

__device__ __forceinline__ uint32_t smem_u32(const void* p) {
    uint32_t a;
    asm("{ .reg .u64 t; cvta.to.shared.u64 t, %1; cvt.u32.u64 %0, t; }" : "=r"(a) : "l"(p));
    return a;
}

__device__ __forceinline__ void mma16816(float d[4], const uint32_t a[4],
                                         const uint32_t b[2]) {
    asm volatile(
        "mma.sync.aligned.m16n8k16.row.col.f32.f16.f16.f32 "
        "{%0,%1,%2,%3}, {%4,%5,%6,%7}, {%8,%9}, {%0,%1,%2,%3};\n"
        : "+f"(d[0]), "+f"(d[1]), "+f"(d[2]), "+f"(d[3])
        : "r"(a[0]), "r"(a[1]), "r"(a[2]), "r"(a[3]), "r"(b[0]), "r"(b[1]));
}

#define LDSM4(r, addr) \
    asm volatile("ldmatrix.sync.aligned.m8n8.x4.shared.b16 {%0,%1,%2,%3}, [%4];" \
                 : "=r"((r)[0]), "=r"((r)[1]), "=r"((r)[2]), "=r"((r)[3]) \
                 : "r"(addr))

// ---------------- edge-weight transpose + f16 ----------------
__global__ void prep_wb(const float* __restrict__ w1, const float* __restrict__ w2,
                        const float* __restrict__ w3, __half* __restrict__ t1,
                        __half* __restrict__ t2, __half* __restrict__ t3) {
    int t = blockIdx.x * 256 + threadIdx.x;
    if (t < 4096) {
        int k = t >> 6, n = t & 63;
        t1[n * 64 + k] = __float2half_rn(w1[t]);
    } else if (t < 12288) {
        int e = t - 4096;
        int k = e >> 7, n = e & 127;
        t2[n * 64 + k] = __float2half_rn(w2[e]);
    } else if (t < 77824) {
        int e = t - 12288;
        int k = e >> 9, n = e & 511;
        t3[n * 128 + k] = __float2half_rn(w3[e]);
    }
}

// ---------------- head-weight transpose + f16 ----------------
__global__ void prep_wf(const float* __restrict__ wf1, const float* __restrict__ wf2,
                        __half* __restrict__ t1, __half* __restrict__ t2) {
    int t = blockIdx.x * 256 + threadIdx.x;
    if (t < 360448) {
        int n = t / 704, k = t - n * 704;
        t1[t] = __float2half_rn(wf1[k * 512 + n]);
    } else {
        int e = t - 360448;
        int n = e >> 9, k = e & 511;
        t2[e] = __float2half_rn(wf2[k * 256 + n]);
    }
}

// ---------------- kNN: REDUX + sorted-pop selection ----------------
// Keys: (hi = ordered-u32(d2), lo = idx m). Order (hi asc, lo asc) == lax.top_k.
// Each lane sorts its 8 keys once (19-CE network); per extraction round:
// 2 REDUX + head compare + 7-pair register shift on the single winning lane.
#define KCE(a, b) { \
    bool sw = (khi[a] > khi[b]) || (khi[a] == khi[b] && klo[a] > klo[b]); \
    unsigned th = sw ? khi[b] : khi[a], tl = sw ? klo[b] : klo[a]; \
    khi[b] = sw ? khi[a] : khi[b]; klo[b] = sw ? klo[a] : klo[b]; \
    khi[a] = th; klo[a] = tl; }
#define KSORT8() \
    KCE(0,1) KCE(2,3) KCE(4,5) KCE(6,7) \
    KCE(0,2) KCE(1,3) KCE(4,6) KCE(5,7) \
    KCE(1,2) KCE(5,6) \
    KCE(0,4) KCE(1,5) KCE(2,6) KCE(3,7) \
    KCE(2,4) KCE(3,5) \
    KCE(1,2) KCE(3,4) KCE(5,6)

__global__ __launch_bounds__(256) void knn_kernel(const float* __restrict__ pos) {
    __shared__ unsigned long long cand[256];
    int point = blockIdx.x;
    int base  = (point >> 11) * N_;
    int tid   = threadIdx.x;
    int w     = tid >> 5, lane = tid & 31;

    float px = pos[point * 3 + 0], py = pos[point * 3 + 1], pz = pos[point * 3 + 2];
    float sqn = fmaf(pz, pz, fmaf(py, py, px * px));

    {
        unsigned khi[8], klo[8];
#pragma unroll
        for (int i = 0; i < 8; i++) {
            int m = (w << 8) + (i << 5) + lane;
            const float* pm = pos + (size_t)(base + m) * 3;
            float mx = pm[0], my = pm[1], mz = pm[2];
            float dot = fmaf(pz, mz, fmaf(py, my, px * mx));
            float sqm = fmaf(mz, mz, fmaf(my, my, mx * mx));
            float d2  = (sqn - 2.f * dot) + sqm;
            unsigned u = __float_as_uint(d2);
            khi[i] = (u & 0x80000000u) ? ~u : (u | 0x80000000u);
            klo[i] = (unsigned)m;
        }
        KSORT8();

#pragma unroll 4
        for (int it = 0; it < K_; it++) {
            unsigned mhi  = __reduce_min_sync(0xffffffffu, khi[0]);
            unsigned prop = (khi[0] == mhi) ? klo[0] : 0xFFFFFFFFu;
            unsigned mlo  = __reduce_min_sync(0xffffffffu, prop);
            if (lane == 0)
                cand[(w << 5) + it] = ((unsigned long long)mhi << 32) | mlo;
            if (prop == mlo) {     // unique winner (idx unique)
#pragma unroll
                for (int i = 0; i < 7; i++) { khi[i] = khi[i + 1]; klo[i] = klo[i + 1]; }
                khi[7] = 0xFFFFFFFFu; klo[7] = 0xFFFFFFFFu;
            }
        }
    }
    __syncthreads();

    if (w == 0) {
        unsigned khi[8], klo[8];
#pragma unroll
        for (int i = 0; i < 8; i++) {
            unsigned long long c = cand[(i << 5) + lane];
            khi[i] = (unsigned)(c >> 32);
            klo[i] = (unsigned)c;
        }
        KSORT8();

#pragma unroll 4
        for (int it = 0; it < K_; it++) {
            unsigned mhi  = __reduce_min_sync(0xffffffffu, khi[0]);
            unsigned prop = (khi[0] == mhi) ? klo[0] : 0xFFFFFFFFu;
            unsigned mlo  = __reduce_min_sync(0xffffffffu, prop);
            if (lane == 0) g_idx[point * K_ + it] = base + (int)mlo;
            if (prop == mlo) {
#pragma unroll
                for (int i = 0; i < 7; i++) { khi[i] = khi[i + 1]; klo[i] = klo[i + 1]; }
                khi[7] = 0xFFFFFFFFu; klo[7] = 0xFFFFFFFFu;
            }
        }
    }
}

// ---------------- batched per-point projections p,q ----------------
template <int CIN, int CMID, int CINP>
__global__ __launch_bounds__(256) void proj_kernel(const float* __restrict__ x,
                                                   const float* __restrict__ wa,
                                                   const float* __restrict__ ba) {
    extern __shared__ __align__(16) float smf[];
    float* wts = smf;
    float* wqs = wts + CMID * CINP;
    float* xs  = wqs + CMID * CINP;
    float* bas = xs + 32 * CINP;
    int tid = threadIdx.x;
    int p0  = blockIdx.x * 32;

    for (int t = tid; t < CIN * CMID; t += 256) {
        int ci = t / CMID, cm = t - ci * CMID;
        float top = wa[t], bot = wa[CIN * CMID + t];
        wts[cm * CINP + ci] = top - bot;
        wqs[cm * CINP + ci] = bot;
    }
    for (int t = tid; t < 32 * CIN; t += 256) {
        int pp = t / CIN, ci = t - pp * CIN;
        xs[pp * CINP + ci] = x[(size_t)(p0 + pp) * CIN + ci];
    }
    if (tid < CMID) bas[tid] = ba[tid];
    __syncthreads();

    constexpr int LANES = 256 / CMID;
    int li = tid / CMID, cm = tid - li * CMID;
    const float* wtr = wts + cm * CINP;
    const float* wqr = wqs + cm * CINP;
    float bias = bas[cm];

    for (int pp = li; pp < 32; pp += LANES) {
        const float* xr = xs + pp * CINP;
        float pa = bias, qa = 0.f;
        if constexpr (CIN % 4 == 0) {
#pragma unroll
            for (int ci = 0; ci < CIN; ci += 4) {
                float4 xv = *(const float4*)(xr + ci);
                float4 wt4 = *(const float4*)(wtr + ci);
                float4 wq4 = *(const float4*)(wqr + ci);
                pa = fmaf(xv.x, wt4.x, pa); qa = fmaf(xv.x, wq4.x, qa);
                pa = fmaf(xv.y, wt4.y, pa); qa = fmaf(xv.y, wq4.y, qa);
                pa = fmaf(xv.z, wt4.z, pa); qa = fmaf(xv.z, wq4.z, qa);
                pa = fmaf(xv.w, wt4.w, pa); qa = fmaf(xv.w, wq4.w, qa);
            }
        } else {
#pragma unroll
            for (int ci = 0; ci < CIN; ci++) {
                float xv = xr[ci];
                pa = fmaf(xv, wtr[ci], pa);
                qa = fmaf(xv, wqr[ci], qa);
            }
        }
        g_p[(size_t)(p0 + pp) * CMID + cm] = pa;
        g_q[(size_t)(p0 + pp) * CMID + cm] = qa;
    }
}

// ---------------- edge blocks: f16 mma + ldmatrix, 256 thr, 2 blocks/SM -------
template <int CMID, int COUT, int NITER>
__global__ __launch_bounds__(256, 2) void edge_mma(const __half* __restrict__ wbT,
                                                   const float* __restrict__ bb,
                                                   float* __restrict__ out) {
    constexpr int PT    = 8;
    constexpr int NT    = 64;
    constexpr int KP    = CMID + 8;
    constexpr int AROWS = PT * 32;
    constexpr int CPR8  = CMID / 8;
    extern __shared__ __align__(16) char smraw[];
    __half* As = (__half*)smraw;
    __half* Bs = As + AROWS * KP;
    int*  nidx = (int*)(Bs + NT * KP);

    int tid = threadIdx.x, w = tid >> 5, lane = tid & 31;
    int p0 = blockIdx.x * PT;

    nidx[tid] = g_idx[p0 * K_ + tid];
    __syncthreads();

#pragma unroll
    for (int i = 0; i < AROWS * CPR8 / 256; i++) {
        int e  = i * 256 + tid;
        int r  = e / CPR8;
        int c0 = (e - r * CPR8) * 8;
        const float* qr = g_q + (size_t)nidx[r] * CMID + c0;
        const float* pr = g_p + (size_t)(p0 + (r >> 5)) * CMID + c0;
        float4 qa = *(const float4*)qr, qb = *(const float4*)(qr + 4);
        float4 pa = *(const float4*)pr, pb = *(const float4*)(pr + 4);
        uint4 pk = { pack_f16x2(lrelu(pa.x + qa.x), lrelu(pa.y + qa.y)),
                     pack_f16x2(lrelu(pa.z + qa.z), lrelu(pa.w + qa.w)),
                     pack_f16x2(lrelu(pb.x + qb.x), lrelu(pb.y + qb.y)),
                     pack_f16x2(lrelu(pb.z + qb.z), lrelu(pb.w + qb.w)) };
        *(uint4*)(As + r * KP + c0) = pk;
    }

    uint32_t aBase = smem_u32(As) +
        (uint32_t)(((w * 32 + (lane & 15)) * KP + (lane >> 4) * 8) * 2);
    uint32_t bBase = smem_u32(Bs) +
        (uint32_t)((((lane & 7) + ((lane >> 4) << 3)) * KP + ((lane >> 3) & 1) * 8) * 2);
    int pglob = p0 + w;

#pragma unroll 1
    for (int it = 0; it < NITER; it++) {
        int n0 = it * NT;
        __syncthreads();
#pragma unroll
        for (int i = 0; i < NT * CPR8 / 256; i++) {
            int e  = i * 256 + tid;
            int r  = e / CPR8;
            int c0 = (e - r * CPR8) * 8;
            *(uint4*)(Bs + r * KP + c0) =
                *(const uint4*)(wbT + (size_t)(n0 + r) * CMID + c0);
        }
        __syncthreads();

        float acc[2][8][4];
#pragma unroll
        for (int mt = 0; mt < 2; mt++)
#pragma unroll
            for (int nt = 0; nt < 8; nt++)
#pragma unroll
                for (int j = 0; j < 4; j++) acc[mt][nt][j] = 0.f;

#pragma unroll 1
        for (int ks = 0; ks < CMID / 16; ks++) {
            uint32_t a0[4], a1[4];
            LDSM4(a0, aBase + ks * 32);
            LDSM4(a1, aBase + 16 * KP * 2 + ks * 32);
#pragma unroll
            for (int ntp = 0; ntp < 4; ntp++) {
                uint32_t b[4];
                LDSM4(b, bBase + ntp * (16 * KP * 2) + ks * 32);
                mma16816(acc[0][2 * ntp],     a0, b + 0);
                mma16816(acc[1][2 * ntp],     a1, b + 0);
                mma16816(acc[0][2 * ntp + 1], a0, b + 2);
                mma16816(acc[1][2 * ntp + 1], a1, b + 2);
            }
        }

#pragma unroll
        for (int nt = 0; nt < 8; nt++) {
            float v0 = fmaxf(fmaxf(acc[0][nt][0], acc[0][nt][2]),
                             fmaxf(acc[1][nt][0], acc[1][nt][2]));
            float v1 = fmaxf(fmaxf(acc[0][nt][1], acc[0][nt][3]),
                             fmaxf(acc[1][nt][1], acc[1][nt][3]));
#pragma unroll
            for (int s = 4; s < 32; s <<= 1) {
                v0 = fmaxf(v0, __shfl_xor_sync(0xffffffffu, v0, s));
                v1 = fmaxf(v1, __shfl_xor_sync(0xffffffffu, v1, s));
            }
            if (lane < 4) {
                int col = n0 + nt * 8 + 2 * lane;
                out[(size_t)pglob * COUT + col]     = lrelu(v0 + bb[col]);
                out[(size_t)pglob * COUT + col + 1] = lrelu(v1 + bb[col + 1]);
            }
        }
    }
}

// ---------------- head1: concat(704) -> 512 via f16 mma, lrelu, h1 f16 --------
__global__ __launch_bounds__(256, 2) void head1_mma(const __half* __restrict__ wT,
                                                    const float* __restrict__ bias) {
    __shared__ __align__(16) __half As[64 * 72];
    __shared__ __align__(16) __half Bs[128 * 72];
    int tid = threadIdx.x, w = tid >> 5, lane = tid & 31;
    int m0 = blockIdx.x * 64, n0 = blockIdx.y * 128;
    int mt = (w >> 1) * 16, ng = (w & 1) * 64;

    float acc[8][4];
#pragma unroll
    for (int nt = 0; nt < 8; nt++)
#pragma unroll
        for (int j = 0; j < 4; j++) acc[nt][j] = 0.f;

    uint32_t aBase = smem_u32(As) +
        (uint32_t)(((mt + (lane & 15)) * 72 + (lane >> 4) * 8) * 2);
    uint32_t bBase = smem_u32(Bs) +
        (uint32_t)(((ng + (lane & 7) + ((lane >> 4) << 3)) * 72 + ((lane >> 3) & 1) * 8) * 2);

#pragma unroll 1
    for (int kc = 0; kc < 11; kc++) {
        const float* src; int stride, off;
        if (kc == 0)      { src = g_x1; stride = 64;  off = 0; }
        else if (kc <= 2) { src = g_x2; stride = 128; off = (kc - 1) * 64; }
        else              { src = g_x3; stride = 512; off = (kc - 3) * 64; }
#pragma unroll
        for (int i = 0; i < 2; i++) {
            int t = i * 256 + tid;
            int r = t >> 3, c0 = (t & 7) * 8;
            const float* sp = src + (size_t)(m0 + r) * stride + off + c0;
            float4 a = *(const float4*)sp, b = *(const float4*)(sp + 4);
            uint4 pk = { pack_f16x2(a.x, a.y), pack_f16x2(a.z, a.w),
                         pack_f16x2(b.x, b.y), pack_f16x2(b.z, b.w) };
            *(uint4*)(As + r * 72 + c0) = pk;
        }
#pragma unroll
        for (int i = 0; i < 4; i++) {
            int t = i * 256 + tid;
            int r = t >> 3, c0 = (t & 7) * 8;
            *(uint4*)(Bs + r * 72 + c0) =
                *(const uint4*)(wT + (size_t)(n0 + r) * 704 + kc * 64 + c0);
        }
        __syncthreads();
#pragma unroll
        for (int ks = 0; ks < 4; ks++) {
            uint32_t a[4];
            LDSM4(a, aBase + ks * 32);
#pragma unroll
            for (int ntp = 0; ntp < 4; ntp++) {
                uint32_t b[4];
                LDSM4(b, bBase + ntp * (16 * 72 * 2) + ks * 32);
                mma16816(acc[2 * ntp],     a, b + 0);
                mma16816(acc[2 * ntp + 1], a, b + 2);
            }
        }
        __syncthreads();
    }

    int gid = lane >> 2, tig = lane & 3;
    int row = m0 + mt + gid;
#pragma unroll
    for (int nt = 0; nt < 8; nt++) {
        int col = n0 + ng + nt * 8 + 2 * tig;
        float b0 = bias[col], b1 = bias[col + 1];
        *(uint32_t*)(g_h1 + (size_t)row * 512 + col) =
            pack_f16x2(lrelu(acc[nt][0] + b0), lrelu(acc[nt][1] + b1));
        *(uint32_t*)(g_h1 + (size_t)(row + 8) * 512 + col) =
            pack_f16x2(lrelu(acc[nt][2] + b0), lrelu(acc[nt][3] + b1));
    }
}

// ---------------- head2: 512 -> 256 via f16 mma, lrelu, h2 fp32 ---------------
__global__ __launch_bounds__(256, 2) void head2_mma(const __half* __restrict__ wT,
                                                    const float* __restrict__ bias) {
    __shared__ __align__(16) __half As[64 * 72];
    __shared__ __align__(16) __half Bs[128 * 72];
    int tid = threadIdx.x, w = tid >> 5, lane = tid & 31;
    int m0 = blockIdx.x * 64, n0 = blockIdx.y * 128;
    int mt = (w >> 1) * 16, ng = (w & 1) * 64;

    float acc[8][4];
#pragma unroll
    for (int nt = 0; nt < 8; nt++)
#pragma unroll
        for (int j = 0; j < 4; j++) acc[nt][j] = 0.f;

    uint32_t aBase = smem_u32(As) +
        (uint32_t)(((mt + (lane & 15)) * 72 + (lane >> 4) * 8) * 2);
    uint32_t bBase = smem_u32(Bs) +
        (uint32_t)(((ng + (lane & 7) + ((lane >> 4) << 3)) * 72 + ((lane >> 3) & 1) * 8) * 2);

#pragma unroll 1
    for (int kc = 0; kc < 8; kc++) {
#pragma unroll
        for (int i = 0; i < 2; i++) {
            int t = i * 256 + tid;
            int r = t >> 3, c0 = (t & 7) * 8;
            *(uint4*)(As + r * 72 + c0) =
                *(const uint4*)(g_h1 + (size_t)(m0 + r) * 512 + kc * 64 + c0);
        }
#pragma unroll
        for (int i = 0; i < 4; i++) {
            int t = i * 256 + tid;
            int r = t >> 3, c0 = (t & 7) * 8;
            *(uint4*)(Bs + r * 72 + c0) =
                *(const uint4*)(wT + (size_t)(n0 + r) * 512 + kc * 64 + c0);
        }
        __syncthreads();
#pragma unroll
        for (int ks = 0; ks < 4; ks++) {
            uint32_t a[4];
            LDSM4(a, aBase + ks * 32);
#pragma unroll
            for (int ntp = 0; ntp < 4; ntp++) {
                uint32_t b[4];
                LDSM4(b, bBase + ntp * (16 * 72 * 2) + ks * 32);
                mma16816(acc[2 * ntp],     a, b + 0);
                mma16816(acc[2 * ntp + 1], a, b + 2);
            }
        }
        __syncthreads();
    }

    int gid = lane >> 2, tig = lane & 3;
    int row = m0 + mt + gid;
#pragma unroll
    for (int nt = 0; nt < 8; nt++) {
        int col = n0 + ng + nt * 8 + 2 * tig;
        float b0 = bias[col], b1 = bias[col + 1];
        g_h2[(size_t)row * 256 + col]           = lrelu(acc[nt][0] + b0);
        g_h2[(size_t)row * 256 + col + 1]       = lrelu(acc[nt][1] + b1);
        g_h2[(size_t)(row + 8) * 256 + col]     = lrelu(acc[nt][2] + b0);
        g_h2[(size_t)(row + 8) * 256 + col + 1] = lrelu(acc[nt][3] + b1);
    }
}

// ---------------- head3: 256 -> 12 (fp32, no lrelu) ----------------
__global__ __launch_bounds__(192) void head3_kernel(const float* __restrict__ wf3,
                                                    const float* __restrict__ bf3,
                                                    float* __restrict__ out) {
    int blk = blockIdx.x, tid = threadIdx.x;
    int r = tid / 12, c = tid - r * 12;
    int row = blk * 16 + r;
    const float* h = g_h2 + (size_t)row * 256;
    float a0 = bf3[c], a1 = 0.f, a2 = 0.f, a3 = 0.f;
#pragma unroll 4
    for (int cm = 0; cm < 256; cm += 4) {
        a0 = fmaf(h[cm + 0], wf3[(cm + 0) * 12 + c], a0);
        a1 = fmaf(h[cm + 1], wf3[(cm + 1) * 12 + c], a1);
        a2 = fmaf(h[cm + 2], wf3[(cm + 2) * 12 + c], a2);
        a3 = fmaf(h[cm + 3], wf3[(cm + 3) * 12 + c], a3);
    }
    out[(size_t)row * 12 + c] = (a0 + a1) + (a2 + a3);
}

// ---------------- launch ----------------
constexpr int SMEM_P1 = (2 * 64 * 4 + 32 * 4 + 64) * 4;
constexpr int SMEM_P2 = (2 * 64 * 68 + 32 * 68 + 64) * 4;
constexpr int SMEM_P3 = (2 * 128 * 132 + 32 * 132 + 128) * 4;
constexpr int SMEM_E12 = (256 * 72 + 64 * 72) * 2 + 256 * 4;
constexpr int SMEM_E3  = (256 * 136 + 64 * 136) * 2 + 256 * 4;

extern "C" void kernel_launch(void* const* d_in, const int* in_sizes, int n_in,
                              void* d_out, int out_size) {
    const float* x   = (const float*)d_in[0];
    const float* pos = (const float*)d_in[1];
    const float* w1a = (const float*)d_in[2];
    const float* b1a = (const float*)d_in[3];
    const float* w1b = (const float*)d_in[4];
    const float* b1b = (const float*)d_in[5];
    const float* w2a = (const float*)d_in[6];
    const float* b2a = (const float*)d_in[7];
    const float* w2b = (const float*)d_in[8];
    const float* b2b = (const float*)d_in[9];
    const float* w3a = (const float*)d_in[10];
    const float* b3a = (const float*)d_in[11];
    const float* w3b = (const float*)d_in[12];
    const float* b3b = (const float*)d_in[13];
    const float* wf1 = (const float*)d_in[14];
    const float* bf1 = (const float*)d_in[15];
    const float* wf2 = (const float*)d_in[16];
    const float* bf2 = (const float*)d_in[17];
    const float* wf3 = (const float*)d_in[18];
    const float* bf3 = (const float*)d_in[19];
    float* out = (float*)d_out;

    float *x1p, *x2p, *x3p;
    __half *wt1p, *wt2p, *wt3p, *wf1Tp, *wf2Tp;
    cudaGetSymbolAddress((void**)&x1p, g_x1);
    cudaGetSymbolAddress((void**)&x2p, g_x2);
    cudaGetSymbolAddress((void**)&x3p, g_x3);
    cudaGetSymbolAddress((void**)&wt1p, g_wbT1);
    cudaGetSymbolAddress((void**)&wt2p, g_wbT2);
    cudaGetSymbolAddress((void**)&wt3p, g_wbT3);
    cudaGetSymbolAddress((void**)&wf1Tp, g_wf1T);
    cudaGetSymbolAddress((void**)&wf2Tp, g_wf2T);

    static bool attr_done = false;
    if (!attr_done) {
        cudaFuncSetAttribute(proj_kernel<128, 128, 132>,
                             cudaFuncAttributeMaxDynamicSharedMemorySize, SMEM_P3);
        cudaFuncSetAttribute(edge_mma<64, 64, 1>,
                             cudaFuncAttributeMaxDynamicSharedMemorySize, SMEM_E12);
        cudaFuncSetAttribute(edge_mma<64, 128, 2>,
                             cudaFuncAttributeMaxDynamicSharedMemorySize, SMEM_E12);
        cudaFuncSetAttribute(edge_mma<128, 512, 8>,
                             cudaFuncAttributeMaxDynamicSharedMemorySize, SMEM_E3);
        attr_done = true;
    }

    // slot 4 is the launch ncu captures -> knn stays there to verify the fix
    proj_kernel<3, 64, 4><<<BN_ / 32, 256, SMEM_P1>>>(x, w1a, b1a);        // 1
    prep_wb<<<304, 256>>>(w1b, w2b, w3b, wt1p, wt2p, wt3p);                // 2
    prep_wf<<<1920, 256>>>(wf1, wf2, wf1Tp, wf2Tp);                        // 3
    knn_kernel<<<BN_, 256>>>(pos);                                         // 4 <- ncu

    // block1: 3 -> 64 -> 64
    edge_mma<64, 64, 1><<<BN_ / 8, 256, SMEM_E12>>>(wt1p, b1b, x1p);
    // block2: 64 -> 64 -> 128
    proj_kernel<64, 64, 68><<<BN_ / 32, 256, SMEM_P2>>>(x1p, w2a, b2a);
    edge_mma<64, 128, 2><<<BN_ / 8, 256, SMEM_E12>>>(wt2p, b2b, x2p);
    // block3: 128 -> 128 -> 512
    proj_kernel<128, 128, 132><<<BN_ / 32, 256, SMEM_P3>>>(x2p, w3a, b3a);
    edge_mma<128, 512, 8><<<BN_ / 8, 256, SMEM_E3>>>(wt3p, b3b, x3p);

    // head: 704 -> 512 (f16 mma) -> 256 (f16 mma) -> 12 (fp32)
    head1_mma<<<dim3(BN_ / 64, 4), 256>>>(wf1Tp, bf1);
    head2_mma<<<dim3(BN_ / 64, 2), 256>>>(wf2Tp, bf2);
    head3_kernel<<<BN_ / 16, 192>>>(wf3, bf3, out);
}